// round 1
// baseline (speedup 1.0000x reference)
#include <cuda_runtime.h>
#include <math.h>

#define BB 2048
#define LL 10
#define VOCAB 1974
#define DD 512
#define HH 8
#define DQK 64
#define DVV 64
#define DI 2048
#define NLAY 6
#define BOARD 70
#define NTOK (BB*LL)       /* 20480 */
#define NBRD (BB*BOARD)    /* 143360 */
#define VPAD 2048

// ---------------- scratch (static device buffers; no allocation) ----------------
__device__ float g_x  [NTOK*DD];          // 10.5M
__device__ float g_xn [NTOK*DD];
__device__ float g_q  [NTOK*DD];
__device__ float g_kv [NTOK*1024];        // self-attn K|V
__device__ float g_ao [NTOK*DD];          // attention output (pre out-proj)
__device__ float g_ckv[146800640];        // 143360*1024 cross K|V (587MB)
__device__ float g_h  [NTOK*DI];          // FFN hidden
__device__ float g_fcw[DD*VPAD];          // padded logits weight
__device__ float g_fcb[VPAD];

// ---------------- embedding ----------------
__global__ void embed_k(const int* __restrict__ moves,
                        const float* __restrict__ emb,
                        const float* __restrict__ pos) {
    int n = blockIdx.x;
    int mv = moves[n];
    int l = n % LL;
    const float* e = emb + (size_t)mv * DD;
    const float* p = pos + (size_t)l * DD;
    float* o = g_x + (size_t)n * DD;
    for (int d = threadIdx.x; d < DD; d += blockDim.x)
        o[d] = e[d] * 22.62741699796952f + p[d];   // sqrt(512)
}

// ---------------- layernorm (row of 512, 256 threads) ----------------
__global__ __launch_bounds__(256) void ln_k(const float* __restrict__ X,
                                            const float* __restrict__ g,
                                            const float* __restrict__ b,
                                            float* __restrict__ Y) {
    int row = blockIdx.x;
    const float2* x2 = (const float2*)(X + (size_t)row * DD);
    float2 v = x2[threadIdx.x];
    float s  = v.x + v.y;
    float ss = v.x * v.x + v.y * v.y;
    #pragma unroll
    for (int o = 16; o; o >>= 1) {
        s  += __shfl_down_sync(0xffffffffu, s,  o);
        ss += __shfl_down_sync(0xffffffffu, ss, o);
    }
    __shared__ float rs[8], rss[8];
    int w = threadIdx.x >> 5;
    if ((threadIdx.x & 31) == 0) { rs[w] = s; rss[w] = ss; }
    __syncthreads();
    if (threadIdx.x == 0) {
        float a = 0.f, c = 0.f;
        #pragma unroll
        for (int i = 0; i < 8; i++) { a += rs[i]; c += rss[i]; }
        rs[0] = a; rss[0] = c;
    }
    __syncthreads();
    float mean = rs[0] * (1.0f / DD);
    float var  = rss[0] * (1.0f / DD) - mean * mean;
    float rstd = rsqrtf(var + 1e-5f);
    float2 gg = ((const float2*)g)[threadIdx.x];
    float2 bb = ((const float2*)b)[threadIdx.x];
    float2 o;
    o.x = (v.x - mean) * rstd * gg.x + bb.x;
    o.y = (v.y - mean) * rstd * gg.y + bb.y;
    ((float2*)(Y + (size_t)row * DD))[threadIdx.x] = o;
}

// ---------------- SGEMM: C[M,Nc] = A[M,K] @ W[K,N] (+bias, epi) ----------------
// epi 0: +bias   1: relu(+bias)   2: +bias+res
#define BM 128
#define BN 128
#define BK 8
#define TM 8
#define TN 8
__global__ __launch_bounds__(256, 2) void sgemm_k(
    const float* __restrict__ A, const float* __restrict__ W,
    const float* __restrict__ bias, const float* __restrict__ res,
    float* __restrict__ C, int M, int N, int K, int Nc, int epi) {
    __shared__ float As[BK][BM];
    __shared__ float Ws[BK][BN];
    int tid = threadIdx.x;
    int tx = tid & 15, ty = tid >> 4;
    int m0 = blockIdx.y * BM, n0 = blockIdx.x * BN;

    int arow = tid >> 1;
    int acol = (tid & 1) * 4;
    int wrow = tid >> 5;
    int wcol = (tid & 31) * 4;
    const float* Aptr = A + (size_t)(m0 + arow) * K + acol;
    const float* Wptr = W + (size_t)wrow * N + n0 + wcol;

    float acc[TM][TN];
    #pragma unroll
    for (int i = 0; i < TM; i++)
        #pragma unroll
        for (int j = 0; j < TN; j++) acc[i][j] = 0.f;

    float4 a4 = *(const float4*)(Aptr);
    float4 w4 = *(const float4*)(Wptr);

    for (int k0 = 0; k0 < K; k0 += BK) {
        As[acol + 0][arow] = a4.x;
        As[acol + 1][arow] = a4.y;
        As[acol + 2][arow] = a4.z;
        As[acol + 3][arow] = a4.w;
        *(float4*)&Ws[wrow][wcol] = w4;
        __syncthreads();

        float4 a4n, w4n;
        if (k0 + BK < K) {
            a4n = *(const float4*)(Aptr + k0 + BK);
            w4n = *(const float4*)(Wptr + (size_t)(k0 + BK) * N);
        }
        #pragma unroll
        for (int kk = 0; kk < BK; kk++) {
            float af[TM], wf[TN];
            #pragma unroll
            for (int i = 0; i < TM; i++) af[i] = As[kk][ty * TM + i];
            #pragma unroll
            for (int j = 0; j < TN; j++) wf[j] = Ws[kk][tx * TN + j];
            #pragma unroll
            for (int i = 0; i < TM; i++)
                #pragma unroll
                for (int j = 0; j < TN; j++)
                    acc[i][j] += af[i] * wf[j];
        }
        __syncthreads();
        a4 = a4n; w4 = w4n;
    }

    #pragma unroll
    for (int i = 0; i < TM; i++) {
        int m = m0 + ty * TM + i;
        size_t rowoff = (size_t)m * Nc;
        #pragma unroll
        for (int j = 0; j < TN; j++) {
            int n = n0 + tx * TN + j;
            if (n < Nc) {
                float v = acc[i][j] + bias[n];
                if (epi == 1) v = fmaxf(v, 0.f);
                else if (epi == 2) v += res[rowoff + n];
                C[rowoff + n] = v;
            }
        }
    }
}

// ---------------- self attention: per (b,h), Lq=Lk=10 ----------------
__global__ __launch_bounds__(128) void selfattn_k(const float* __restrict__ Q,
                                                  const float* __restrict__ KV,
                                                  const int* __restrict__ lengths,
                                                  float* __restrict__ O) {
    int b = blockIdx.x, h = blockIdx.y;
    __shared__ float q[LL][65], k[LL][65], v[LL][65], s[LL][11];
    int tid = threadIdx.x;
    int len = lengths[b];
    for (int idx = tid; idx < LL * 64; idx += 128) {
        int i = idx >> 6, d = idx & 63;
        size_t qoff = ((size_t)(b * LL + i)) * DD + h * 64 + d;
        size_t koff = ((size_t)(b * LL + i)) * 1024 + h * 64 + d;
        q[i][d] = Q[qoff];
        k[i][d] = KV[koff];
        v[i][d] = KV[koff + 512];
    }
    __syncthreads();
    for (int idx = tid; idx < LL * LL; idx += 128) {
        int i = idx / LL, j = idx % LL;
        float acc = 0.f;
        #pragma unroll
        for (int d = 0; d < 64; d++) acc += q[i][d] * k[j][d];
        acc *= 0.125f;
        if (j > i || j >= len) acc = -1e30f;
        s[i][j] = acc;
    }
    __syncthreads();
    if (tid < LL) {
        float mx = -1e30f;
        #pragma unroll
        for (int j = 0; j < LL; j++) mx = fmaxf(mx, s[tid][j]);
        float sum = 0.f;
        #pragma unroll
        for (int j = 0; j < LL; j++) { float e = expf(s[tid][j] - mx); s[tid][j] = e; sum += e; }
        float inv = 1.0f / sum;
        #pragma unroll
        for (int j = 0; j < LL; j++) s[tid][j] *= inv;
    }
    __syncthreads();
    for (int idx = tid; idx < LL * 64; idx += 128) {
        int i = idx >> 6, d = idx & 63;
        float acc = 0.f;
        #pragma unroll
        for (int j = 0; j < LL; j++) acc += s[i][j] * v[j][d];
        O[((size_t)(b * LL + i)) * DD + h * 64 + d] = acc;
    }
}

// ---------------- cross attention: per (b,h), Lq=10, Lk=70 ----------------
__global__ __launch_bounds__(256) void crossattn_k(const float* __restrict__ Q,
                                                   const float* __restrict__ CKV,
                                                   float* __restrict__ O) {
    int b = blockIdx.x, h = blockIdx.y;
    __shared__ float q[LL][65], kk[BOARD][65], vv[BOARD][65], s[LL][71];
    int tid = threadIdx.x;
    for (int idx = tid; idx < LL * 64; idx += 256) {
        int i = idx >> 6, d = idx & 63;
        q[i][d] = Q[((size_t)(b * LL + i)) * DD + h * 64 + d];
    }
    for (int idx = tid; idx < BOARD * 64; idx += 256) {
        int j = idx >> 6, d = idx & 63;
        size_t off = ((size_t)(b * BOARD + j)) * 1024 + h * 64 + d;
        kk[j][d] = CKV[off];
        vv[j][d] = CKV[off + 512];
    }
    __syncthreads();
    for (int idx = tid; idx < LL * BOARD; idx += 256) {
        int i = idx / BOARD, j = idx % BOARD;
        float acc = 0.f;
        #pragma unroll
        for (int d = 0; d < 64; d++) acc += q[i][d] * kk[j][d];
        s[i][j] = acc * 0.125f;
    }
    __syncthreads();
    if (tid < LL) {
        float mx = -1e30f;
        for (int j = 0; j < BOARD; j++) mx = fmaxf(mx, s[tid][j]);
        float sum = 0.f;
        for (int j = 0; j < BOARD; j++) { float e = expf(s[tid][j] - mx); s[tid][j] = e; sum += e; }
        float inv = 1.0f / sum;
        for (int j = 0; j < BOARD; j++) s[tid][j] *= inv;
    }
    __syncthreads();
    for (int idx = tid; idx < LL * 64; idx += 256) {
        int i = idx >> 6, d = idx & 63;
        float acc = 0.f;
        #pragma unroll
        for (int j = 0; j < BOARD; j++) acc += s[i][j] * vv[j][d];
        O[((size_t)(b * LL + i)) * DD + h * 64 + d] = acc;
    }
}

// ---------------- pad fc_w (512x1974) -> g_fcw (512x2048), fc_b -> g_fcb ----------------
__global__ void pad_fc_k(const float* __restrict__ fcw, const float* __restrict__ fcb) {
    int idx = blockIdx.x * blockDim.x + threadIdx.x;  // 512*2048 total
    int kr = idx / VPAD, n = idx % VPAD;
    g_fcw[idx] = (n < VOCAB) ? fcw[(size_t)kr * VOCAB + n] : 0.f;
    if (idx < VPAD) g_fcb[idx] = (idx < VOCAB) ? fcb[idx] : 0.f;
}

// ---------------- host ----------------
static void gemm(const float* A, const float* W, const float* bias, const float* res,
                 float* C, int M, int N, int K, int Nc, int epi) {
    dim3 grid(N / BN, M / BM);
    sgemm_k<<<grid, 256>>>(A, W, bias, res, C, M, N, K, Nc, epi);
}

extern "C" void kernel_launch(void* const* d_in, const int* in_sizes, int n_in,
                              void* d_out, int out_size) {
    const int*   moves   = (const int*)d_in[0];
    const int*   lengths = (const int*)d_in[1];
    const float* boards  = (const float*)d_in[2];
    const float* emb     = (const float*)d_in[3];
    const float* pos     = (const float*)d_in[4];
    const float* sa_ln_g = (const float*)d_in[5];
    const float* sa_ln_b = (const float*)d_in[6];
    const float* sa_wq   = (const float*)d_in[7];
    const float* sa_bq   = (const float*)d_in[8];
    const float* sa_wkv  = (const float*)d_in[9];
    const float* sa_bkv  = (const float*)d_in[10];
    const float* sa_wo   = (const float*)d_in[11];
    const float* sa_bo   = (const float*)d_in[12];
    const float* ca_ln_g = (const float*)d_in[13];
    const float* ca_ln_b = (const float*)d_in[14];
    const float* ca_wq   = (const float*)d_in[15];
    const float* ca_bq   = (const float*)d_in[16];
    const float* ca_wkv  = (const float*)d_in[17];
    const float* ca_bkv  = (const float*)d_in[18];
    const float* ca_wo   = (const float*)d_in[19];
    const float* ca_bo   = (const float*)d_in[20];
    const float* ff_ln_g = (const float*)d_in[21];
    const float* ff_ln_b = (const float*)d_in[22];
    const float* ff_w1   = (const float*)d_in[23];
    const float* ff_b1   = (const float*)d_in[24];
    const float* ff_w2   = (const float*)d_in[25];
    const float* ff_b2   = (const float*)d_in[26];
    const float* fin_g   = (const float*)d_in[27];
    const float* fin_b   = (const float*)d_in[28];
    const float* fc_w    = (const float*)d_in[29];
    const float* fc_b    = (const float*)d_in[30];
    float* out = (float*)d_out;

    float *px, *pxn, *pq, *pkv, *pao, *pckv, *ph, *pfcw, *pfcb;
    cudaGetSymbolAddress((void**)&px,   g_x);
    cudaGetSymbolAddress((void**)&pxn,  g_xn);
    cudaGetSymbolAddress((void**)&pq,   g_q);
    cudaGetSymbolAddress((void**)&pkv,  g_kv);
    cudaGetSymbolAddress((void**)&pao,  g_ao);
    cudaGetSymbolAddress((void**)&pckv, g_ckv);
    cudaGetSymbolAddress((void**)&ph,   g_h);
    cudaGetSymbolAddress((void**)&pfcw, g_fcw);
    cudaGetSymbolAddress((void**)&pfcb, g_fcb);

    embed_k<<<NTOK, 128>>>(moves, emb, pos);
    pad_fc_k<<<(DD * VPAD) / 512, 512>>>(fc_w, fc_b);

    for (int i = 0; i < NLAY; i++) {
        // ---- self attention block ----
        ln_k<<<NTOK, 256>>>(px, sa_ln_g + i * DD, sa_ln_b + i * DD, pxn);
        gemm(pxn, sa_wq + (size_t)i * DD * 512, sa_bq + i * 512, nullptr, pq,
             NTOK, 512, DD, 512, 0);
        gemm(pxn, sa_wkv + (size_t)i * DD * 1024, sa_bkv + i * 1024, nullptr, pkv,
             NTOK, 1024, DD, 1024, 0);
        selfattn_k<<<dim3(BB, HH), 128>>>(pq, pkv, lengths, pao);
        gemm(pao, sa_wo + (size_t)i * 512 * DD, sa_bo + i * DD, px, px,
             NTOK, DD, 512, DD, 2);

        // ---- cross attention block ----
        ln_k<<<NTOK, 256>>>(px, ca_ln_g + i * DD, ca_ln_b + i * DD, pxn);
        gemm(pxn, ca_wq + (size_t)i * DD * 512, ca_bq + i * 512, nullptr, pq,
             NTOK, 512, DD, 512, 0);
        gemm(boards, ca_wkv + (size_t)i * DD * 1024, ca_bkv + i * 1024, nullptr, pckv,
             NBRD, 1024, DD, 1024, 0);
        crossattn_k<<<dim3(BB, HH), 256>>>(pq, pckv, pao);
        gemm(pao, ca_wo + (size_t)i * 512 * DD, ca_bo + i * DD, px, px,
             NTOK, DD, 512, DD, 2);

        // ---- FFN ----
        ln_k<<<NTOK, 256>>>(px, ff_ln_g + i * DD, ff_ln_b + i * DD, pxn);
        gemm(pxn, ff_w1 + (size_t)i * DD * DI, ff_b1 + i * DI, nullptr, ph,
             NTOK, DI, DD, DI, 1);
        gemm(ph, ff_w2 + (size_t)i * DI * DD, ff_b2 + i * DD, px, px,
             NTOK, DD, DI, DD, 2);
    }

    ln_k<<<NTOK, 256>>>(px, fin_g, fin_b, pxn);
    gemm(pxn, pfcw, pfcb, nullptr, out, NTOK, VPAD, DD, VOCAB, 0);
}

// round 2
// speedup vs baseline: 1.6484x; 1.6484x over previous
#include <cuda_runtime.h>
#include <cuda_bf16.h>
#include <math.h>

#define BB 2048
#define LL 10
#define VOCAB 1974
#define DD 512
#define HH 8
#define DI 2048
#define NLAY 6
#define BOARD 70
#define NTOK (BB*LL)       /* 20480 */
#define NBRD (BB*BOARD)    /* 143360 */
#define VPAD 2048

// ---- weight arena offsets (elements) ----
#define OFF_SAWQ  0
#define OFF_SAWKV 1572864
#define OFF_SAWO  4718592
#define OFF_CAWQ  6291456
#define OFF_CAWKV 7864320
#define OFF_CAWO  11010048
#define OFF_FFW1  12582912
#define OFF_FFW2  18874368
#define OFF_FCW   25165824
#define WTOT      26214400

// ---------------- scratch (static device buffers) ----------------
__device__ float g_x  [NTOK*DD];
__device__ float g_q  [NTOK*DD];
__device__ float g_kv [NTOK*1024];
__device__ float g_ckv[146800640];            // 143360*1024
__device__ float g_fcb[VPAD];
__device__ __nv_bfloat16 g_xnh[NTOK*DD],  g_xnl[NTOK*DD];
__device__ __nv_bfloat16 g_aoh[NTOK*DD],  g_aol[NTOK*DD];
__device__ __nv_bfloat16 g_hh [NTOK*DI],  g_hl [NTOK*DI];
__device__ __nv_bfloat16 g_bh [73400320], g_bl [73400320];   // boards split
__device__ __nv_bfloat16 g_wh [WTOT],     g_wl [WTOT];       // all weights split

// ---------------- embedding ----------------
__global__ void embed_k(const int* __restrict__ moves,
                        const float* __restrict__ emb,
                        const float* __restrict__ pos) {
    int n = blockIdx.x;
    int mv = moves[n];
    int l = n % LL;
    const float* e = emb + (size_t)mv * DD;
    const float* p = pos + (size_t)l * DD;
    float* o = g_x + (size_t)n * DD;
    for (int d = threadIdx.x; d < DD; d += blockDim.x)
        o[d] = e[d] * 22.62741699796952f + p[d];
}

// ---------------- generic fp32 -> (hi,lo) bf16 split ----------------
__global__ void split_k(const float* __restrict__ X,
                        __nv_bfloat16* __restrict__ H,
                        __nv_bfloat16* __restrict__ L, int n) {
    int i = blockIdx.x * blockDim.x + threadIdx.x;
    if (i < n) {
        float x = X[i];
        __nv_bfloat16 h = __float2bfloat16_rn(x);
        H[i] = h;
        L[i] = __float2bfloat16_rn(x - __bfloat162float(h));
    }
}

// ---------------- pad + split fc weight, copy fc bias ----------------
__global__ void pad_fc_k(const float* __restrict__ fcw, const float* __restrict__ fcb) {
    int idx = blockIdx.x * blockDim.x + threadIdx.x;   // over 512*2048
    int kr = idx / VPAD, n = idx % VPAD;
    float v = (n < VOCAB) ? fcw[(size_t)kr * VOCAB + n] : 0.f;
    __nv_bfloat16 h = __float2bfloat16_rn(v);
    g_wh[OFF_FCW + idx] = h;
    g_wl[OFF_FCW + idx] = __float2bfloat16_rn(v - __bfloat162float(h));
    if (idx < VPAD) g_fcb[idx] = (idx < VOCAB) ? fcb[idx] : 0.f;
}

// ---------------- layernorm -> split bf16 output ----------------
__global__ __launch_bounds__(256) void ln_split_k(const float* __restrict__ X,
                                                  const float* __restrict__ g,
                                                  const float* __restrict__ b,
                                                  __nv_bfloat16* __restrict__ Yh,
                                                  __nv_bfloat16* __restrict__ Yl) {
    int row = blockIdx.x;
    const float2* x2 = (const float2*)(X + (size_t)row * DD);
    float2 v = x2[threadIdx.x];
    float s  = v.x + v.y;
    float ss = v.x * v.x + v.y * v.y;
    #pragma unroll
    for (int o = 16; o; o >>= 1) {
        s  += __shfl_down_sync(0xffffffffu, s,  o);
        ss += __shfl_down_sync(0xffffffffu, ss, o);
    }
    __shared__ float rs[8], rss[8];
    int w = threadIdx.x >> 5;
    if ((threadIdx.x & 31) == 0) { rs[w] = s; rss[w] = ss; }
    __syncthreads();
    if (threadIdx.x == 0) {
        float a = 0.f, c = 0.f;
        #pragma unroll
        for (int i = 0; i < 8; i++) { a += rs[i]; c += rss[i]; }
        rs[0] = a; rss[0] = c;
    }
    __syncthreads();
    float mean = rs[0] * (1.0f / DD);
    float var  = rss[0] * (1.0f / DD) - mean * mean;
    float rstd = rsqrtf(var + 1e-5f);
    float2 gg = ((const float2*)g)[threadIdx.x];
    float2 bb = ((const float2*)b)[threadIdx.x];
    float o0 = (v.x - mean) * rstd * gg.x + bb.x;
    float o1 = (v.y - mean) * rstd * gg.y + bb.y;
    size_t base = (size_t)row * DD + threadIdx.x * 2;
    __nv_bfloat16 h0 = __float2bfloat16_rn(o0);
    __nv_bfloat16 h1 = __float2bfloat16_rn(o1);
    Yh[base]   = h0; Yl[base]   = __float2bfloat16_rn(o0 - __bfloat162float(h0));
    Yh[base+1] = h1; Yl[base+1] = __float2bfloat16_rn(o1 - __bfloat162float(h1));
}

// ---------------- split-3 bf16 tensor-core GEMM ----------------
// C = A @ W, A = Ah+Al (M x K), W = Wh+Wl (K x N); three mma passes:
// Ah*Wh, Ah*Wl, Al*Wh, fp32 accum. Block 128x128, Ktile 32, 8 warps.
// epi: 0 = +bias -> C fp32; 1 = relu(+bias) -> (Chi,Clo) split; 2 = +bias+res -> C fp32
__global__ __launch_bounds__(256, 2) void bgemm_k(
    const __nv_bfloat16* __restrict__ Ah, const __nv_bfloat16* __restrict__ Al,
    const __nv_bfloat16* __restrict__ Wh, const __nv_bfloat16* __restrict__ Wl,
    const float* __restrict__ bias, const float* __restrict__ res,
    float* __restrict__ C, __nv_bfloat16* __restrict__ Chi, __nv_bfloat16* __restrict__ Clo,
    int M, int N, int K, int Nc, int epi)
{
    __shared__ __nv_bfloat16 As[128][40];
    __shared__ __nv_bfloat16 Ws[32][136];
    const int tid  = threadIdx.x;
    const int lane = tid & 31;
    const int warp = tid >> 5;
    const int wm = (warp & 1) * 64;
    const int wn = (warp >> 1) * 32;
    const int m0 = blockIdx.y * 128;
    const int n0 = blockIdx.x * 128;

    const int arow = tid >> 1;
    const int acol = (tid & 1) * 16;
    const int wrow = tid >> 3;
    const int wcol = (tid & 7) * 16;

    float acc[4][4][4];
    #pragma unroll
    for (int i = 0; i < 4; i++)
        #pragma unroll
        for (int j = 0; j < 4; j++)
            #pragma unroll
            for (int q = 0; q < 4; q++) acc[i][j][q] = 0.f;

    const int KT  = K >> 5;
    const int NIT = 3 * KT;

    uint4 ra0, ra1, rw0, rw1;
    {
        const __nv_bfloat16* ap = Ah + (size_t)(m0 + arow) * K + acol;
        ra0 = *(const uint4*)ap; ra1 = *(const uint4*)(ap + 8);
        const __nv_bfloat16* wp = Wh + (size_t)wrow * N + n0 + wcol;
        rw0 = *(const uint4*)wp; rw1 = *(const uint4*)(wp + 8);
    }

    for (int it = 0; it < NIT; it++) {
        *(uint4*)&As[arow][acol]     = ra0;
        *(uint4*)&As[arow][acol + 8] = ra1;
        *(uint4*)&Ws[wrow][wcol]     = rw0;
        *(uint4*)&Ws[wrow][wcol + 8] = rw1;
        __syncthreads();

        if (it + 1 < NIT) {
            int nit = it + 1;
            int p  = nit / KT;
            int k0 = (nit - p * KT) << 5;
            const __nv_bfloat16* Ap = (p == 2) ? Al : Ah;
            const __nv_bfloat16* Wp = (p == 1) ? Wl : Wh;
            const __nv_bfloat16* ap = Ap + (size_t)(m0 + arow) * K + k0 + acol;
            ra0 = *(const uint4*)ap; ra1 = *(const uint4*)(ap + 8);
            const __nv_bfloat16* wp = Wp + (size_t)(k0 + wrow) * N + n0 + wcol;
            rw0 = *(const uint4*)wp; rw1 = *(const uint4*)(wp + 8);
        }

        #pragma unroll
        for (int ks = 0; ks < 2; ks++) {
            unsigned aF[4][4], bF[4][2];
            #pragma unroll
            for (int mt = 0; mt < 4; mt++) {
                unsigned addr = (unsigned)__cvta_generic_to_shared(
                    &As[wm + mt * 16 + (lane & 15)][ks * 16 + (lane >> 4) * 8]);
                asm volatile("ldmatrix.sync.aligned.m8n8.x4.shared.b16 {%0,%1,%2,%3}, [%4];"
                    : "=r"(aF[mt][0]), "=r"(aF[mt][1]), "=r"(aF[mt][2]), "=r"(aF[mt][3])
                    : "r"(addr));
            }
            #pragma unroll
            for (int nt = 0; nt < 4; nt++) {
                unsigned addr = (unsigned)__cvta_generic_to_shared(
                    &Ws[ks * 16 + (lane & 15)][wn + nt * 8]);
                asm volatile("ldmatrix.sync.aligned.m8n8.x2.trans.shared.b16 {%0,%1}, [%2];"
                    : "=r"(bF[nt][0]), "=r"(bF[nt][1]) : "r"(addr));
            }
            #pragma unroll
            for (int mt = 0; mt < 4; mt++)
                #pragma unroll
                for (int nt = 0; nt < 4; nt++) {
                    asm volatile(
                        "mma.sync.aligned.m16n8k16.row.col.f32.bf16.bf16.f32 "
                        "{%0,%1,%2,%3}, {%4,%5,%6,%7}, {%8,%9}, {%0,%1,%2,%3};"
                        : "+f"(acc[mt][nt][0]), "+f"(acc[mt][nt][1]),
                          "+f"(acc[mt][nt][2]), "+f"(acc[mt][nt][3])
                        : "r"(aF[mt][0]), "r"(aF[mt][1]), "r"(aF[mt][2]), "r"(aF[mt][3]),
                          "r"(bF[nt][0]), "r"(bF[nt][1]));
                }
        }
        __syncthreads();
    }

    #pragma unroll
    for (int mt = 0; mt < 4; mt++) {
        int r0 = m0 + wm + mt * 16 + (lane >> 2);
        #pragma unroll
        for (int nt = 0; nt < 4; nt++) {
            int c0 = n0 + wn + nt * 8 + (lane & 3) * 2;
            #pragma unroll
            for (int q = 0; q < 4; q++) {
                int r = r0 + (q >> 1) * 8;
                int c = c0 + (q & 1);
                if (c < Nc) {
                    float v = acc[mt][nt][q] + bias[c];
                    size_t off = (size_t)r * Nc + c;
                    if (epi == 2) v += res[off];
                    if (epi == 1) {
                        v = fmaxf(v, 0.f);
                        __nv_bfloat16 h = __float2bfloat16_rn(v);
                        Chi[off] = h;
                        Clo[off] = __float2bfloat16_rn(v - __bfloat162float(h));
                    } else {
                        C[off] = v;
                    }
                }
            }
        }
    }
}

// ---------------- self attention: per (b,h), Lq=Lk=10, split output ----------------
__global__ __launch_bounds__(128) void selfattn_k(const float* __restrict__ Q,
                                                  const float* __restrict__ KV,
                                                  const int* __restrict__ lengths,
                                                  __nv_bfloat16* __restrict__ Oh,
                                                  __nv_bfloat16* __restrict__ Ol) {
    int b = blockIdx.x, h = blockIdx.y;
    __shared__ float q[LL][65], k[LL][65], v[LL][65], s[LL][11];
    int tid = threadIdx.x;
    int len = lengths[b];
    for (int idx = tid; idx < LL * 64; idx += 128) {
        int i = idx >> 6, d = idx & 63;
        size_t qoff = ((size_t)(b * LL + i)) * DD + h * 64 + d;
        size_t koff = ((size_t)(b * LL + i)) * 1024 + h * 64 + d;
        q[i][d] = Q[qoff];
        k[i][d] = KV[koff];
        v[i][d] = KV[koff + 512];
    }
    __syncthreads();
    for (int idx = tid; idx < LL * LL; idx += 128) {
        int i = idx / LL, j = idx % LL;
        float acc = 0.f;
        #pragma unroll
        for (int d = 0; d < 64; d++) acc += q[i][d] * k[j][d];
        acc *= 0.125f;
        if (j > i || j >= len) acc = -1e30f;
        s[i][j] = acc;
    }
    __syncthreads();
    if (tid < LL) {
        float mx = -1e30f;
        #pragma unroll
        for (int j = 0; j < LL; j++) mx = fmaxf(mx, s[tid][j]);
        float sum = 0.f;
        #pragma unroll
        for (int j = 0; j < LL; j++) { float e = expf(s[tid][j] - mx); s[tid][j] = e; sum += e; }
        float inv = 1.0f / sum;
        #pragma unroll
        for (int j = 0; j < LL; j++) s[tid][j] *= inv;
    }
    __syncthreads();
    for (int idx = tid; idx < LL * 64; idx += 128) {
        int i = idx >> 6, d = idx & 63;
        float acc = 0.f;
        #pragma unroll
        for (int j = 0; j < LL; j++) acc += s[i][j] * v[j][d];
        size_t off = ((size_t)(b * LL + i)) * DD + h * 64 + d;
        __nv_bfloat16 hv = __float2bfloat16_rn(acc);
        Oh[off] = hv;
        Ol[off] = __float2bfloat16_rn(acc - __bfloat162float(hv));
    }
}

// ---------------- cross attention: per (b,h), Lq=10, Lk=70, split output ----------------
__global__ __launch_bounds__(256) void crossattn_k(const float* __restrict__ Q,
                                                   const float* __restrict__ CKV,
                                                   __nv_bfloat16* __restrict__ Oh,
                                                   __nv_bfloat16* __restrict__ Ol) {
    int b = blockIdx.x, h = blockIdx.y;
    __shared__ float q[LL][65], kk[BOARD][65], vv[BOARD][65], s[LL][71];
    int tid = threadIdx.x;
    for (int idx = tid; idx < LL * 64; idx += 256) {
        int i = idx >> 6, d = idx & 63;
        q[i][d] = Q[((size_t)(b * LL + i)) * DD + h * 64 + d];
    }
    for (int idx = tid; idx < BOARD * 64; idx += 256) {
        int j = idx >> 6, d = idx & 63;
        size_t off = ((size_t)(b * BOARD + j)) * 1024 + h * 64 + d;
        kk[j][d] = CKV[off];
        vv[j][d] = CKV[off + 512];
    }
    __syncthreads();
    for (int idx = tid; idx < LL * BOARD; idx += 256) {
        int i = idx / BOARD, j = idx % BOARD;
        float acc = 0.f;
        #pragma unroll
        for (int d = 0; d < 64; d++) acc += q[i][d] * kk[j][d];
        s[i][j] = acc * 0.125f;
    }
    __syncthreads();
    if (tid < LL) {
        float mx = -1e30f;
        for (int j = 0; j < BOARD; j++) mx = fmaxf(mx, s[tid][j]);
        float sum = 0.f;
        for (int j = 0; j < BOARD; j++) { float e = expf(s[tid][j] - mx); s[tid][j] = e; sum += e; }
        float inv = 1.0f / sum;
        for (int j = 0; j < BOARD; j++) s[tid][j] *= inv;
    }
    __syncthreads();
    for (int idx = tid; idx < LL * 64; idx += 256) {
        int i = idx >> 6, d = idx & 63;
        float acc = 0.f;
        #pragma unroll
        for (int j = 0; j < BOARD; j++) acc += s[i][j] * vv[j][d];
        size_t off = ((size_t)(b * LL + i)) * DD + h * 64 + d;
        __nv_bfloat16 hv = __float2bfloat16_rn(acc);
        Oh[off] = hv;
        Ol[off] = __float2bfloat16_rn(acc - __bfloat162float(hv));
    }
}

// ---------------- host ----------------
static void bgemm(const __nv_bfloat16* Ah, const __nv_bfloat16* Al,
                  const __nv_bfloat16* Wh, const __nv_bfloat16* Wl,
                  const float* bias, const float* res,
                  float* C, __nv_bfloat16* Chi, __nv_bfloat16* Clo,
                  int M, int N, int K, int Nc, int epi) {
    dim3 grid(N / 128, M / 128);
    bgemm_k<<<grid, 256>>>(Ah, Al, Wh, Wl, bias, res, C, Chi, Clo, M, N, K, Nc, epi);
}

extern "C" void kernel_launch(void* const* d_in, const int* in_sizes, int n_in,
                              void* d_out, int out_size) {
    const int*   moves   = (const int*)d_in[0];
    const int*   lengths = (const int*)d_in[1];
    const float* boards  = (const float*)d_in[2];
    const float* emb     = (const float*)d_in[3];
    const float* pos     = (const float*)d_in[4];
    const float* sa_ln_g = (const float*)d_in[5];
    const float* sa_ln_b = (const float*)d_in[6];
    const float* sa_wq   = (const float*)d_in[7];
    const float* sa_bq   = (const float*)d_in[8];
    const float* sa_wkv  = (const float*)d_in[9];
    const float* sa_bkv  = (const float*)d_in[10];
    const float* sa_wo   = (const float*)d_in[11];
    const float* sa_bo   = (const float*)d_in[12];
    const float* ca_ln_g = (const float*)d_in[13];
    const float* ca_ln_b = (const float*)d_in[14];
    const float* ca_wq   = (const float*)d_in[15];
    const float* ca_bq   = (const float*)d_in[16];
    const float* ca_wkv  = (const float*)d_in[17];
    const float* ca_bkv  = (const float*)d_in[18];
    const float* ca_wo   = (const float*)d_in[19];
    const float* ca_bo   = (const float*)d_in[20];
    const float* ff_ln_g = (const float*)d_in[21];
    const float* ff_ln_b = (const float*)d_in[22];
    const float* ff_w1   = (const float*)d_in[23];
    const float* ff_b1   = (const float*)d_in[24];
    const float* ff_w2   = (const float*)d_in[25];
    const float* ff_b2   = (const float*)d_in[26];
    const float* fin_g   = (const float*)d_in[27];
    const float* fin_b   = (const float*)d_in[28];
    const float* fc_w    = (const float*)d_in[29];
    const float* fc_b    = (const float*)d_in[30];
    float* out = (float*)d_out;

    float *px, *pq, *pkv, *pckv, *pfcb;
    __nv_bfloat16 *pxnh, *pxnl, *paoh, *paol, *phh, *phl, *pbh, *pbl, *pwh, *pwl;
    cudaGetSymbolAddress((void**)&px,   g_x);
    cudaGetSymbolAddress((void**)&pq,   g_q);
    cudaGetSymbolAddress((void**)&pkv,  g_kv);
    cudaGetSymbolAddress((void**)&pckv, g_ckv);
    cudaGetSymbolAddress((void**)&pfcb, g_fcb);
    cudaGetSymbolAddress((void**)&pxnh, g_xnh);
    cudaGetSymbolAddress((void**)&pxnl, g_xnl);
    cudaGetSymbolAddress((void**)&paoh, g_aoh);
    cudaGetSymbolAddress((void**)&paol, g_aol);
    cudaGetSymbolAddress((void**)&phh,  g_hh);
    cudaGetSymbolAddress((void**)&phl,  g_hl);
    cudaGetSymbolAddress((void**)&pbh,  g_bh);
    cudaGetSymbolAddress((void**)&pbl,  g_bl);
    cudaGetSymbolAddress((void**)&pwh,  g_wh);
    cudaGetSymbolAddress((void**)&pwl,  g_wl);

    embed_k<<<NTOK, 128>>>(moves, emb, pos);
    // one-time splits
    split_k<<<(73400320 + 511) / 512, 512>>>(boards, pbh, pbl, 73400320);
    split_k<<<(1572864 + 511) / 512, 512>>>(sa_wq,  pwh + OFF_SAWQ,  pwl + OFF_SAWQ,  1572864);
    split_k<<<(3145728 + 511) / 512, 512>>>(sa_wkv, pwh + OFF_SAWKV, pwl + OFF_SAWKV, 3145728);
    split_k<<<(1572864 + 511) / 512, 512>>>(sa_wo,  pwh + OFF_SAWO,  pwl + OFF_SAWO,  1572864);
    split_k<<<(1572864 + 511) / 512, 512>>>(ca_wq,  pwh + OFF_CAWQ,  pwl + OFF_CAWQ,  1572864);
    split_k<<<(3145728 + 511) / 512, 512>>>(ca_wkv, pwh + OFF_CAWKV, pwl + OFF_CAWKV, 3145728);
    split_k<<<(1572864 + 511) / 512, 512>>>(ca_wo,  pwh + OFF_CAWO,  pwl + OFF_CAWO,  1572864);
    split_k<<<(6291456 + 511) / 512, 512>>>(ff_w1,  pwh + OFF_FFW1,  pwl + OFF_FFW1,  6291456);
    split_k<<<(6291456 + 511) / 512, 512>>>(ff_w2,  pwh + OFF_FFW2,  pwl + OFF_FFW2,  6291456);
    pad_fc_k<<<(DD * VPAD) / 512, 512>>>(fc_w, fc_b);

    for (int i = 0; i < NLAY; i++) {
        size_t oQ  = (size_t)i * 262144;
        size_t oKV = (size_t)i * 524288;
        size_t oF  = (size_t)i * 1048576;

        // ---- self attention ----
        ln_split_k<<<NTOK, 256>>>(px, sa_ln_g + i * DD, sa_ln_b + i * DD, pxnh, pxnl);
        bgemm(pxnh, pxnl, pwh + OFF_SAWQ + oQ, pwl + OFF_SAWQ + oQ,
              sa_bq + i * 512, nullptr, pq, nullptr, nullptr, NTOK, 512, 512, 512, 0);
        bgemm(pxnh, pxnl, pwh + OFF_SAWKV + oKV, pwl + OFF_SAWKV + oKV,
              sa_bkv + i * 1024, nullptr, pkv, nullptr, nullptr, NTOK, 1024, 512, 1024, 0);
        selfattn_k<<<dim3(BB, HH), 128>>>(pq, pkv, lengths, paoh, paol);
        bgemm(paoh, paol, pwh + OFF_SAWO + oQ, pwl + OFF_SAWO + oQ,
              sa_bo + i * DD, px, px, nullptr, nullptr, NTOK, 512, 512, 512, 2);

        // ---- cross attention ----
        ln_split_k<<<NTOK, 256>>>(px, ca_ln_g + i * DD, ca_ln_b + i * DD, pxnh, pxnl);
        bgemm(pxnh, pxnl, pwh + OFF_CAWQ + oQ, pwl + OFF_CAWQ + oQ,
              ca_bq + i * 512, nullptr, pq, nullptr, nullptr, NTOK, 512, 512, 512, 0);
        bgemm(pbh, pbl, pwh + OFF_CAWKV + oKV, pwl + OFF_CAWKV + oKV,
              ca_bkv + i * 1024, nullptr, pckv, nullptr, nullptr, NBRD, 1024, 512, 1024, 0);
        crossattn_k<<<dim3(BB, HH), 256>>>(pq, pckv, paoh, paol);
        bgemm(paoh, paol, pwh + OFF_CAWO + oQ, pwl + OFF_CAWO + oQ,
              ca_bo + i * DD, px, px, nullptr, nullptr, NTOK, 512, 512, 512, 2);

        // ---- FFN ----
        ln_split_k<<<NTOK, 256>>>(px, ff_ln_g + i * DD, ff_ln_b + i * DD, pxnh, pxnl);
        bgemm(pxnh, pxnl, pwh + OFF_FFW1 + oF, pwl + OFF_FFW1 + oF,
              ff_b1 + i * DI, nullptr, nullptr, phh, phl, NTOK, DI, 512, DI, 1);
        bgemm(phh, phl, pwh + OFF_FFW2 + oF, pwl + OFF_FFW2 + oF,
              ff_b2 + i * DD, px, px, nullptr, nullptr, NTOK, 512, DI, 512, 2);
    }

    ln_split_k<<<NTOK, 256>>>(px, fin_g, fin_b, pxnh, pxnl);
    bgemm(pxnh, pxnl, pwh + OFF_FCW, pwl + OFF_FCW,
          pfcb, nullptr, out, nullptr, nullptr, NTOK, VPAD, 512, VOCAB, 0);
}

// round 3
// speedup vs baseline: 1.6585x; 1.0061x over previous
#include <cuda_runtime.h>
#include <cuda_bf16.h>
#include <math.h>

#define BB 2048
#define LL 10
#define VOCAB 1974
#define DD 512
#define HH 8
#define DI 2048
#define NLAY 6
#define BOARD 70
#define NTOK (BB*LL)       /* 20480 */
#define NBRD (BB*BOARD)    /* 143360 */
#define VPAD 2048

// ---- weight arena offsets (elements) ----
#define OFF_SAWQ  0
#define OFF_SAWKV 1572864
#define OFF_SAWO  4718592
#define OFF_CAWQ  6291456
#define OFF_CAWKV 7864320
#define OFF_CAWO  11010048
#define OFF_FFW1  12582912
#define OFF_FFW2  18874368
#define OFF_FCW   25165824
#define WTOT      26214400

// ---------------- scratch (static device buffers) ----------------
__device__ float g_x  [NTOK*DD];
__device__ float g_q  [NTOK*DD];
__device__ float g_kv [NTOK*1024];
__device__ float g_ckv[146800640];            // 143360*1024
__device__ float g_fcb[VPAD];
__device__ __nv_bfloat16 g_xnh[NTOK*DD],  g_xnl[NTOK*DD];
__device__ __nv_bfloat16 g_aoh[NTOK*DD],  g_aol[NTOK*DD];
__device__ __nv_bfloat16 g_hh [NTOK*DI],  g_hl [NTOK*DI];
__device__ __nv_bfloat16 g_bh [73400320], g_bl [73400320];   // boards split
__device__ __nv_bfloat16 g_wh [WTOT],     g_wl [WTOT];       // all weights split

// ---------------- embedding ----------------
__global__ void embed_k(const int* __restrict__ moves,
                        const float* __restrict__ emb,
                        const float* __restrict__ pos) {
    int n = blockIdx.x;
    int mv = moves[n];
    int l = n % LL;
    const float* e = emb + (size_t)mv * DD;
    const float* p = pos + (size_t)l * DD;
    float* o = g_x + (size_t)n * DD;
    for (int d = threadIdx.x; d < DD; d += blockDim.x)
        o[d] = e[d] * 22.62741699796952f + p[d];
}

// ---------------- generic fp32 -> (hi,lo) bf16 split ----------------
__global__ void split_k(const float* __restrict__ X,
                        __nv_bfloat16* __restrict__ H,
                        __nv_bfloat16* __restrict__ L, int n) {
    int i = blockIdx.x * blockDim.x + threadIdx.x;
    if (i < n) {
        float x = X[i];
        __nv_bfloat16 h = __float2bfloat16_rn(x);
        H[i] = h;
        L[i] = __float2bfloat16_rn(x - __bfloat162float(h));
    }
}

// ---------------- pad + split fc weight, copy fc bias ----------------
__global__ void pad_fc_k(const float* __restrict__ fcw, const float* __restrict__ fcb) {
    int idx = blockIdx.x * blockDim.x + threadIdx.x;   // over 512*2048
    int kr = idx / VPAD, n = idx % VPAD;
    float v = (n < VOCAB) ? fcw[(size_t)kr * VOCAB + n] : 0.f;
    __nv_bfloat16 h = __float2bfloat16_rn(v);
    g_wh[OFF_FCW + idx] = h;
    g_wl[OFF_FCW + idx] = __float2bfloat16_rn(v - __bfloat162float(h));
    if (idx < VPAD) g_fcb[idx] = (idx < VOCAB) ? fcb[idx] : 0.f;
}

// ---------------- layernorm -> split bf16 output ----------------
__global__ __launch_bounds__(256) void ln_split_k(const float* __restrict__ X,
                                                  const float* __restrict__ g,
                                                  const float* __restrict__ b,
                                                  __nv_bfloat16* __restrict__ Yh,
                                                  __nv_bfloat16* __restrict__ Yl) {
    int row = blockIdx.x;
    const float2* x2 = (const float2*)(X + (size_t)row * DD);
    float2 v = x2[threadIdx.x];
    float s  = v.x + v.y;
    float ss = v.x * v.x + v.y * v.y;
    #pragma unroll
    for (int o = 16; o; o >>= 1) {
        s  += __shfl_down_sync(0xffffffffu, s,  o);
        ss += __shfl_down_sync(0xffffffffu, ss, o);
    }
    __shared__ float rs[8], rss[8];
    int w = threadIdx.x >> 5;
    if ((threadIdx.x & 31) == 0) { rs[w] = s; rss[w] = ss; }
    __syncthreads();
    if (threadIdx.x == 0) {
        float a = 0.f, c = 0.f;
        #pragma unroll
        for (int i = 0; i < 8; i++) { a += rs[i]; c += rss[i]; }
        rs[0] = a; rss[0] = c;
    }
    __syncthreads();
    float mean = rs[0] * (1.0f / DD);
    float var  = rss[0] * (1.0f / DD) - mean * mean;
    float rstd = rsqrtf(var + 1e-5f);
    float2 gg = ((const float2*)g)[threadIdx.x];
    float2 bb = ((const float2*)b)[threadIdx.x];
    float o0 = (v.x - mean) * rstd * gg.x + bb.x;
    float o1 = (v.y - mean) * rstd * gg.y + bb.y;
    size_t base = (size_t)row * DD + threadIdx.x * 2;
    __nv_bfloat16 h0 = __float2bfloat16_rn(o0);
    __nv_bfloat16 h1 = __float2bfloat16_rn(o1);
    Yh[base]   = h0; Yl[base]   = __float2bfloat16_rn(o0 - __bfloat162float(h0));
    Yh[base+1] = h1; Yl[base+1] = __float2bfloat16_rn(o1 - __bfloat162float(h1));
}

// ---------------- split-3 bf16 tensor-core GEMM ----------------
// C = A @ W, A = Ah+Al (M x K), W = Wh+Wl (K x N); three mma passes:
// Ah*Wh, Ah*Wl, Al*Wh, fp32 accum. Block 128x128, Ktile 32, 8 warps.
// epi: 0 = +bias -> C fp32; 1 = relu(+bias) -> (Chi,Clo) split; 2 = +bias+res -> C fp32
__global__ __launch_bounds__(256, 2) void bgemm_k(
    const __nv_bfloat16* __restrict__ Ah, const __nv_bfloat16* __restrict__ Al,
    const __nv_bfloat16* __restrict__ Wh, const __nv_bfloat16* __restrict__ Wl,
    const float* __restrict__ bias, const float* __restrict__ res,
    float* __restrict__ C, __nv_bfloat16* __restrict__ Chi, __nv_bfloat16* __restrict__ Clo,
    int M, int N, int K, int Nc, int epi)
{
    __shared__ __nv_bfloat16 As[128][40];
    __shared__ __nv_bfloat16 Ws[32][136];
    const int tid  = threadIdx.x;
    const int lane = tid & 31;
    const int warp = tid >> 5;
    const int wm = (warp & 1) * 64;
    const int wn = (warp >> 1) * 32;
    const int m0 = blockIdx.y * 128;
    const int n0 = blockIdx.x * 128;

    const int arow = tid >> 1;
    const int acol = (tid & 1) * 16;
    const int wrow = tid >> 3;
    const int wcol = (tid & 7) * 16;

    float acc[4][4][4];
    #pragma unroll
    for (int i = 0; i < 4; i++)
        #pragma unroll
        for (int j = 0; j < 4; j++)
            #pragma unroll
            for (int q = 0; q < 4; q++) acc[i][j][q] = 0.f;

    const int KT  = K >> 5;
    const int NIT = 3 * KT;

    uint4 ra0, ra1, rw0, rw1;
    {
        const __nv_bfloat16* ap = Ah + (size_t)(m0 + arow) * K + acol;
        ra0 = *(const uint4*)ap; ra1 = *(const uint4*)(ap + 8);
        const __nv_bfloat16* wp = Wh + (size_t)wrow * N + n0 + wcol;
        rw0 = *(const uint4*)wp; rw1 = *(const uint4*)(wp + 8);
    }

    for (int it = 0; it < NIT; it++) {
        *(uint4*)&As[arow][acol]     = ra0;
        *(uint4*)&As[arow][acol + 8] = ra1;
        *(uint4*)&Ws[wrow][wcol]     = rw0;
        *(uint4*)&Ws[wrow][wcol + 8] = rw1;
        __syncthreads();

        if (it + 1 < NIT) {
            int nit = it + 1;
            int p  = nit / KT;
            int k0 = (nit - p * KT) << 5;
            const __nv_bfloat16* Ap = (p == 2) ? Al : Ah;
            const __nv_bfloat16* Wp = (p == 1) ? Wl : Wh;
            const __nv_bfloat16* ap = Ap + (size_t)(m0 + arow) * K + k0 + acol;
            ra0 = *(const uint4*)ap; ra1 = *(const uint4*)(ap + 8);
            const __nv_bfloat16* wp = Wp + (size_t)(k0 + wrow) * N + n0 + wcol;
            rw0 = *(const uint4*)wp; rw1 = *(const uint4*)(wp + 8);
        }

        #pragma unroll
        for (int ks = 0; ks < 2; ks++) {
            unsigned aF[4][4], bF[4][2];
            #pragma unroll
            for (int mt = 0; mt < 4; mt++) {
                unsigned addr = (unsigned)__cvta_generic_to_shared(
                    &As[wm + mt * 16 + (lane & 15)][ks * 16 + (lane >> 4) * 8]);
                asm volatile("ldmatrix.sync.aligned.m8n8.x4.shared.b16 {%0,%1,%2,%3}, [%4];"
                    : "=r"(aF[mt][0]), "=r"(aF[mt][1]), "=r"(aF[mt][2]), "=r"(aF[mt][3])
                    : "r"(addr));
            }
            #pragma unroll
            for (int nt = 0; nt < 4; nt++) {
                unsigned addr = (unsigned)__cvta_generic_to_shared(
                    &Ws[ks * 16 + (lane & 15)][wn + nt * 8]);
                asm volatile("ldmatrix.sync.aligned.m8n8.x2.trans.shared.b16 {%0,%1}, [%2];"
                    : "=r"(bF[nt][0]), "=r"(bF[nt][1]) : "r"(addr));
            }
            #pragma unroll
            for (int mt = 0; mt < 4; mt++)
                #pragma unroll
                for (int nt = 0; nt < 4; nt++) {
                    asm volatile(
                        "mma.sync.aligned.m16n8k16.row.col.f32.bf16.bf16.f32 "
                        "{%0,%1,%2,%3}, {%4,%5,%6,%7}, {%8,%9}, {%0,%1,%2,%3};"
                        : "+f"(acc[mt][nt][0]), "+f"(acc[mt][nt][1]),
                          "+f"(acc[mt][nt][2]), "+f"(acc[mt][nt][3])
                        : "r"(aF[mt][0]), "r"(aF[mt][1]), "r"(aF[mt][2]), "r"(aF[mt][3]),
                          "r"(bF[nt][0]), "r"(bF[nt][1]));
                }
        }
        __syncthreads();
    }

    #pragma unroll
    for (int mt = 0; mt < 4; mt++) {
        int r0 = m0 + wm + mt * 16 + (lane >> 2);
        #pragma unroll
        for (int nt = 0; nt < 4; nt++) {
            int c0 = n0 + wn + nt * 8 + (lane & 3) * 2;
            #pragma unroll
            for (int q = 0; q < 4; q++) {
                int r = r0 + (q >> 1) * 8;
                int c = c0 + (q & 1);
                if (c < Nc) {
                    float v = acc[mt][nt][q] + bias[c];
                    size_t off = (size_t)r * Nc + c;
                    if (epi == 2) v += res[off];
                    if (epi == 1) {
                        v = fmaxf(v, 0.f);
                        __nv_bfloat16 h = __float2bfloat16_rn(v);
                        Chi[off] = h;
                        Clo[off] = __float2bfloat16_rn(v - __bfloat162float(h));
                    } else {
                        C[off] = v;
                    }
                }
            }
        }
    }
}

// ---------------- self attention: per (b,h), Lq=Lk=10, split output ----------------
__global__ __launch_bounds__(128) void selfattn_k(const float* __restrict__ Q,
                                                  const float* __restrict__ KV,
                                                  const int* __restrict__ lengths,
                                                  __nv_bfloat16* __restrict__ Oh,
                                                  __nv_bfloat16* __restrict__ Ol) {
    int b = blockIdx.x, h = blockIdx.y;
    __shared__ float q[LL][65], k[LL][65], v[LL][65], s[LL][11];
    int tid = threadIdx.x;
    int len = lengths[b];
    for (int idx = tid; idx < LL * 64; idx += 128) {
        int i = idx >> 6, d = idx & 63;
        size_t qoff = ((size_t)(b * LL + i)) * DD + h * 64 + d;
        size_t koff = ((size_t)(b * LL + i)) * 1024 + h * 64 + d;
        q[i][d] = Q[qoff];
        k[i][d] = KV[koff];
        v[i][d] = KV[koff + 512];
    }
    __syncthreads();
    for (int idx = tid; idx < LL * LL; idx += 128) {
        int i = idx / LL, j = idx % LL;
        float acc = 0.f;
        #pragma unroll
        for (int d = 0; d < 64; d++) acc += q[i][d] * k[j][d];
        acc *= 0.125f;
        if (j > i || j >= len) acc = -1e30f;
        s[i][j] = acc;
    }
    __syncthreads();
    if (tid < LL) {
        float mx = -1e30f;
        #pragma unroll
        for (int j = 0; j < LL; j++) mx = fmaxf(mx, s[tid][j]);
        float sum = 0.f;
        #pragma unroll
        for (int j = 0; j < LL; j++) { float e = expf(s[tid][j] - mx); s[tid][j] = e; sum += e; }
        float inv = 1.0f / sum;
        #pragma unroll
        for (int j = 0; j < LL; j++) s[tid][j] *= inv;
    }
    __syncthreads();
    for (int idx = tid; idx < LL * 64; idx += 128) {
        int i = idx >> 6, d = idx & 63;
        float acc = 0.f;
        #pragma unroll
        for (int j = 0; j < LL; j++) acc += s[i][j] * v[j][d];
        size_t off = ((size_t)(b * LL + i)) * DD + h * 64 + d;
        __nv_bfloat16 hv = __float2bfloat16_rn(acc);
        Oh[off] = hv;
        Ol[off] = __float2bfloat16_rn(acc - __bfloat162float(hv));
    }
}

// ---------------- cross attention: per (b,h), Lq=10, Lk=70, split output ----------------
__global__ __launch_bounds__(256) void crossattn_k(const float* __restrict__ Q,
                                                   const float* __restrict__ CKV,
                                                   __nv_bfloat16* __restrict__ Oh,
                                                   __nv_bfloat16* __restrict__ Ol) {
    int b = blockIdx.x, h = blockIdx.y;
    __shared__ float q[LL][65], kk[BOARD][65], vv[BOARD][65], s[LL][71];
    int tid = threadIdx.x;
    for (int idx = tid; idx < LL * 64; idx += 256) {
        int i = idx >> 6, d = idx & 63;
        q[i][d] = Q[((size_t)(b * LL + i)) * DD + h * 64 + d];
    }
    for (int idx = tid; idx < BOARD * 64; idx += 256) {
        int j = idx >> 6, d = idx & 63;
        size_t off = ((size_t)(b * BOARD + j)) * 1024 + h * 64 + d;
        kk[j][d] = CKV[off];
        vv[j][d] = CKV[off + 512];
    }
    __syncthreads();
    for (int idx = tid; idx < LL * BOARD; idx += 256) {
        int i = idx / BOARD, j = idx % BOARD;
        float acc = 0.f;
        #pragma unroll
        for (int d = 0; d < 64; d++) acc += q[i][d] * kk[j][d];
        s[i][j] = acc * 0.125f;
    }
    __syncthreads();
    if (tid < LL) {
        float mx = -1e30f;
        for (int j = 0; j < BOARD; j++) mx = fmaxf(mx, s[tid][j]);
        float sum = 0.f;
        for (int j = 0; j < BOARD; j++) { float e = expf(s[tid][j] - mx); s[tid][j] = e; sum += e; }
        float inv = 1.0f / sum;
        for (int j = 0; j < BOARD; j++) s[tid][j] *= inv;
    }
    __syncthreads();
    for (int idx = tid; idx < LL * 64; idx += 256) {
        int i = idx >> 6, d = idx & 63;
        float acc = 0.f;
        #pragma unroll
        for (int j = 0; j < BOARD; j++) acc += s[i][j] * vv[j][d];
        size_t off = ((size_t)(b * LL + i)) * DD + h * 64 + d;
        __nv_bfloat16 hv = __float2bfloat16_rn(acc);
        Oh[off] = hv;
        Ol[off] = __float2bfloat16_rn(acc - __bfloat162float(hv));
    }
}

// ---------------- host ----------------
static void bgemm(const __nv_bfloat16* Ah, const __nv_bfloat16* Al,
                  const __nv_bfloat16* Wh, const __nv_bfloat16* Wl,
                  const float* bias, const float* res,
                  float* C, __nv_bfloat16* Chi, __nv_bfloat16* Clo,
                  int M, int N, int K, int Nc, int epi) {
    dim3 grid(N / 128, M / 128);
    bgemm_k<<<grid, 256>>>(Ah, Al, Wh, Wl, bias, res, C, Chi, Clo, M, N, K, Nc, epi);
}

extern "C" void kernel_launch(void* const* d_in, const int* in_sizes, int n_in,
                              void* d_out, int out_size) {
    const int*   moves   = (const int*)d_in[0];
    const int*   lengths = (const int*)d_in[1];
    const float* boards  = (const float*)d_in[2];
    const float* emb     = (const float*)d_in[3];
    const float* pos     = (const float*)d_in[4];
    const float* sa_ln_g = (const float*)d_in[5];
    const float* sa_ln_b = (const float*)d_in[6];
    const float* sa_wq   = (const float*)d_in[7];
    const float* sa_bq   = (const float*)d_in[8];
    const float* sa_wkv  = (const float*)d_in[9];
    const float* sa_bkv  = (const float*)d_in[10];
    const float* sa_wo   = (const float*)d_in[11];
    const float* sa_bo   = (const float*)d_in[12];
    const float* ca_ln_g = (const float*)d_in[13];
    const float* ca_ln_b = (const float*)d_in[14];
    const float* ca_wq   = (const float*)d_in[15];
    const float* ca_bq   = (const float*)d_in[16];
    const float* ca_wkv  = (const float*)d_in[17];
    const float* ca_bkv  = (const float*)d_in[18];
    const float* ca_wo   = (const float*)d_in[19];
    const float* ca_bo   = (const float*)d_in[20];
    const float* ff_ln_g = (const float*)d_in[21];
    const float* ff_ln_b = (const float*)d_in[22];
    const float* ff_w1   = (const float*)d_in[23];
    const float* ff_b1   = (const float*)d_in[24];
    const float* ff_w2   = (const float*)d_in[25];
    const float* ff_b2   = (const float*)d_in[26];
    const float* fin_g   = (const float*)d_in[27];
    const float* fin_b   = (const float*)d_in[28];
    const float* fc_w    = (const float*)d_in[29];
    const float* fc_b    = (const float*)d_in[30];
    float* out = (float*)d_out;

    float *px, *pq, *pkv, *pckv, *pfcb;
    __nv_bfloat16 *pxnh, *pxnl, *paoh, *paol, *phh, *phl, *pbh, *pbl, *pwh, *pwl;
    cudaGetSymbolAddress((void**)&px,   g_x);
    cudaGetSymbolAddress((void**)&pq,   g_q);
    cudaGetSymbolAddress((void**)&pkv,  g_kv);
    cudaGetSymbolAddress((void**)&pckv, g_ckv);
    cudaGetSymbolAddress((void**)&pfcb, g_fcb);
    cudaGetSymbolAddress((void**)&pxnh, g_xnh);
    cudaGetSymbolAddress((void**)&pxnl, g_xnl);
    cudaGetSymbolAddress((void**)&paoh, g_aoh);
    cudaGetSymbolAddress((void**)&paol, g_aol);
    cudaGetSymbolAddress((void**)&phh,  g_hh);
    cudaGetSymbolAddress((void**)&phl,  g_hl);
    cudaGetSymbolAddress((void**)&pbh,  g_bh);
    cudaGetSymbolAddress((void**)&pbl,  g_bl);
    cudaGetSymbolAddress((void**)&pwh,  g_wh);
    cudaGetSymbolAddress((void**)&pwl,  g_wl);

    embed_k<<<NTOK, 128>>>(moves, emb, pos);
    // one-time splits
    split_k<<<(73400320 + 511) / 512, 512>>>(boards, pbh, pbl, 73400320);
    split_k<<<(1572864 + 511) / 512, 512>>>(sa_wq,  pwh + OFF_SAWQ,  pwl + OFF_SAWQ,  1572864);
    split_k<<<(3145728 + 511) / 512, 512>>>(sa_wkv, pwh + OFF_SAWKV, pwl + OFF_SAWKV, 3145728);
    split_k<<<(1572864 + 511) / 512, 512>>>(sa_wo,  pwh + OFF_SAWO,  pwl + OFF_SAWO,  1572864);
    split_k<<<(1572864 + 511) / 512, 512>>>(ca_wq,  pwh + OFF_CAWQ,  pwl + OFF_CAWQ,  1572864);
    split_k<<<(3145728 + 511) / 512, 512>>>(ca_wkv, pwh + OFF_CAWKV, pwl + OFF_CAWKV, 3145728);
    split_k<<<(1572864 + 511) / 512, 512>>>(ca_wo,  pwh + OFF_CAWO,  pwl + OFF_CAWO,  1572864);
    split_k<<<(6291456 + 511) / 512, 512>>>(ff_w1,  pwh + OFF_FFW1,  pwl + OFF_FFW1,  6291456);
    split_k<<<(6291456 + 511) / 512, 512>>>(ff_w2,  pwh + OFF_FFW2,  pwl + OFF_FFW2,  6291456);
    pad_fc_k<<<(DD * VPAD) / 512, 512>>>(fc_w, fc_b);

    for (int i = 0; i < NLAY; i++) {
        size_t oQ  = (size_t)i * 262144;
        size_t oKV = (size_t)i * 524288;
        size_t oF  = (size_t)i * 1048576;

        // ---- self attention ----
        ln_split_k<<<NTOK, 256>>>(px, sa_ln_g + i * DD, sa_ln_b + i * DD, pxnh, pxnl);
        bgemm(pxnh, pxnl, pwh + OFF_SAWQ + oQ, pwl + OFF_SAWQ + oQ,
              sa_bq + i * 512, nullptr, pq, nullptr, nullptr, NTOK, 512, 512, 512, 0);
        bgemm(pxnh, pxnl, pwh + OFF_SAWKV + oKV, pwl + OFF_SAWKV + oKV,
              sa_bkv + i * 1024, nullptr, pkv, nullptr, nullptr, NTOK, 1024, 512, 1024, 0);
        selfattn_k<<<dim3(BB, HH), 128>>>(pq, pkv, lengths, paoh, paol);
        bgemm(paoh, paol, pwh + OFF_SAWO + oQ, pwl + OFF_SAWO + oQ,
              sa_bo + i * DD, px, px, nullptr, nullptr, NTOK, 512, 512, 512, 2);

        // ---- cross attention ----
        ln_split_k<<<NTOK, 256>>>(px, ca_ln_g + i * DD, ca_ln_b + i * DD, pxnh, pxnl);
        bgemm(pxnh, pxnl, pwh + OFF_CAWQ + oQ, pwl + OFF_CAWQ + oQ,
              ca_bq + i * 512, nullptr, pq, nullptr, nullptr, NTOK, 512, 512, 512, 0);
        bgemm(pbh, pbl, pwh + OFF_CAWKV + oKV, pwl + OFF_CAWKV + oKV,
              ca_bkv + i * 1024, nullptr, pckv, nullptr, nullptr, NBRD, 1024, 512, 1024, 0);
        crossattn_k<<<dim3(BB, HH), 256>>>(pq, pckv, paoh, paol);
        bgemm(paoh, paol, pwh + OFF_CAWO + oQ, pwl + OFF_CAWO + oQ,
              ca_bo + i * DD, px, px, nullptr, nullptr, NTOK, 512, 512, 512, 2);

        // ---- FFN ----
        ln_split_k<<<NTOK, 256>>>(px, ff_ln_g + i * DD, ff_ln_b + i * DD, pxnh, pxnl);
        bgemm(pxnh, pxnl, pwh + OFF_FFW1 + oF, pwl + OFF_FFW1 + oF,
              ff_b1 + i * DI, nullptr, nullptr, phh, phl, NTOK, DI, 512, DI, 1);
        bgemm(phh, phl, pwh + OFF_FFW2 + oF, pwl + OFF_FFW2 + oF,
              ff_b2 + i * DD, px, px, nullptr, nullptr, NTOK, 512, DI, 512, 2);
    }

    ln_split_k<<<NTOK, 256>>>(px, fin_g, fin_b, pxnh, pxnl);
    bgemm(pxnh, pxnl, pwh + OFF_FCW, pwl + OFF_FCW,
          pfcb, nullptr, out, nullptr, nullptr, NTOK, VPAD, 512, VOCAB, 0);
}

// round 4
// speedup vs baseline: 3.1383x; 1.8923x over previous
#include <cuda_runtime.h>
#include <cuda_fp16.h>
#include <math.h>

#define BB 2048
#define LL 10
#define VOCAB 1974
#define DD 512
#define HH 8
#define DI 2048
#define NLAY 6
#define BOARD 70
#define NTOK (BB*LL)       /* 20480 */
#define NBRD (BB*BOARD)    /* 143360 */
#define VPAD 2048

// ---- weight arena offsets (elements) ----
#define OFF_SAWQ  0
#define OFF_SAWKV 1572864
#define OFF_SAWO  4718592
#define OFF_CAWQ  6291456
#define OFF_CAWKV 7864320
#define OFF_CAWO  11010048
#define OFF_FFW1  12582912
#define OFF_FFW2  18874368
#define OFF_FCW   25165824
#define WTOT      26214400

// ---------------- scratch (static device buffers) ----------------
__device__ float  g_x  [NTOK*DD];
__device__ float  g_fcb[VPAD];
__device__ __half g_xn [NTOK*DD];
__device__ __half g_q  [NTOK*DD];
__device__ __half g_kv [NTOK*1024];
__device__ __half g_ao [NTOK*DD];
__device__ __half g_h  [NTOK*DI];
__device__ __half g_ckv[(size_t)NBRD*1024];
__device__ __half g_bf [(size_t)NBRD*DD];
__device__ __half g_wf [WTOT];

// ---------------- one-shot weight conversion (single launch) ----------------
__global__ void wconv_k(const float* __restrict__ sawq, const float* __restrict__ sawkv,
                        const float* __restrict__ sawo, const float* __restrict__ cawq,
                        const float* __restrict__ cawkv, const float* __restrict__ cawo,
                        const float* __restrict__ ffw1, const float* __restrict__ ffw2) {
    size_t i = (size_t)blockIdx.x * blockDim.x + threadIdx.x;   // < OFF_FCW
    const float* src; size_t off;
    if      (i < OFF_SAWKV) { src = sawq;  off = i - OFF_SAWQ; }
    else if (i < OFF_SAWO)  { src = sawkv; off = i - OFF_SAWKV; }
    else if (i < OFF_CAWQ)  { src = sawo;  off = i - OFF_SAWO; }
    else if (i < OFF_CAWKV) { src = cawq;  off = i - OFF_CAWQ; }
    else if (i < OFF_CAWO)  { src = cawkv; off = i - OFF_CAWKV; }
    else if (i < OFF_FFW1)  { src = cawo;  off = i - OFF_CAWO; }
    else if (i < OFF_FFW2)  { src = ffw1;  off = i - OFF_FFW1; }
    else                    { src = ffw2;  off = i - OFF_FFW2; }
    g_wf[i] = __float2half_rn(src[off]);
}

__global__ void bconv_k(const float* __restrict__ boards) {
    size_t i = (size_t)blockIdx.x * blockDim.x + threadIdx.x;
    g_bf[i] = __float2half_rn(boards[i]);
}

__global__ void pad_fc_k(const float* __restrict__ fcw, const float* __restrict__ fcb) {
    int idx = blockIdx.x * blockDim.x + threadIdx.x;   // over 512*2048
    int kr = idx / VPAD, n = idx % VPAD;
    float v = (n < VOCAB) ? fcw[(size_t)kr * VOCAB + n] : 0.f;
    g_wf[OFF_FCW + idx] = __float2half_rn(v);
    if (idx < VPAD) g_fcb[idx] = (idx < VOCAB) ? fcb[idx] : 0.f;
}

// ---------------- embedding ----------------
__global__ void embed_k(const int* __restrict__ moves,
                        const float* __restrict__ emb,
                        const float* __restrict__ pos) {
    int n = blockIdx.x;
    int mv = moves[n];
    int l = n % LL;
    const float* e = emb + (size_t)mv * DD;
    const float* p = pos + (size_t)l * DD;
    float* o = g_x + (size_t)n * DD;
    for (int d = threadIdx.x; d < DD; d += blockDim.x)
        o[d] = e[d] * 22.62741699796952f + p[d];
}

// ---------------- layernorm -> fp16 ----------------
__global__ __launch_bounds__(256) void ln_k(const float* __restrict__ X,
                                            const float* __restrict__ g,
                                            const float* __restrict__ b,
                                            __half* __restrict__ Y) {
    int row = blockIdx.x;
    const float2* x2 = (const float2*)(X + (size_t)row * DD);
    float2 v = x2[threadIdx.x];
    float s  = v.x + v.y;
    float ss = v.x * v.x + v.y * v.y;
    #pragma unroll
    for (int o = 16; o; o >>= 1) {
        s  += __shfl_down_sync(0xffffffffu, s,  o);
        ss += __shfl_down_sync(0xffffffffu, ss, o);
    }
    __shared__ float rs[8], rss[8];
    int w = threadIdx.x >> 5;
    if ((threadIdx.x & 31) == 0) { rs[w] = s; rss[w] = ss; }
    __syncthreads();
    if (threadIdx.x == 0) {
        float a = 0.f, c = 0.f;
        #pragma unroll
        for (int i = 0; i < 8; i++) { a += rs[i]; c += rss[i]; }
        rs[0] = a; rss[0] = c;
    }
    __syncthreads();
    float mean = rs[0] * (1.0f / DD);
    float var  = rss[0] * (1.0f / DD) - mean * mean;
    float rstd = rsqrtf(var + 1e-5f);
    float2 gg = ((const float2*)g)[threadIdx.x];
    float2 bb = ((const float2*)b)[threadIdx.x];
    size_t base = (size_t)row * DD + threadIdx.x * 2;
    Y[base]     = __float2half_rn((v.x - mean) * rstd * gg.x + bb.x);
    Y[base + 1] = __float2half_rn((v.y - mean) * rstd * gg.y + bb.y);
}

// ---------------- fp16 tensor-core GEMM, cp.async double-buffered ----------------
// C = A(MxK,f16) @ W(KxN,f16) + bias; epi: 0 +bias->f32  1 relu->f16  2 +bias+res->f32  3 +bias->f16
__global__ __launch_bounds__(256, 2) void hgemm_k(
    const __half* __restrict__ A, const __half* __restrict__ W,
    const float* __restrict__ bias, const float* __restrict__ res,
    float* __restrict__ Cf, __half* __restrict__ Ch,
    int M, int N, int K, int Nc, int epi)
{
    __shared__ __half As[2][128][40];
    __shared__ __half Ws[2][32][136];
    const int tid  = threadIdx.x;
    const int lane = tid & 31;
    const int warp = tid >> 5;
    const int wm = (warp & 1) * 64;
    const int wn = (warp >> 1) * 32;
    const int m0 = blockIdx.y * 128;
    const int n0 = blockIdx.x * 128;

    const int arow = tid >> 1;
    const int acol = (tid & 1) * 16;
    const int wrow = tid >> 3;
    const int wcol = (tid & 7) * 16;

    const __half* Abase = A + (size_t)(m0 + arow) * K + acol;
    const __half* Wbase = W + (size_t)wrow * N + n0 + wcol;

    float acc[4][4][4];
    #pragma unroll
    for (int i = 0; i < 4; i++)
        #pragma unroll
        for (int j = 0; j < 4; j++)
            #pragma unroll
            for (int q = 0; q < 4; q++) acc[i][j][q] = 0.f;

    const int KT = K >> 5;

    #define LOAD_STAGE(s, kt) do {                                                   \
        unsigned da = (unsigned)__cvta_generic_to_shared(&As[s][arow][acol]);        \
        const __half* sa = Abase + (kt) * 32;                                        \
        asm volatile("cp.async.cg.shared.global [%0], [%1], 16;\n"                   \
                     "cp.async.cg.shared.global [%2], [%3], 16;"                     \
                     :: "r"(da), "l"(sa), "r"(da + 16), "l"(sa + 8));                \
        unsigned dw = (unsigned)__cvta_generic_to_shared(&Ws[s][wrow][wcol]);        \
        const __half* sw = Wbase + (size_t)((kt) * 32) * N;                          \
        asm volatile("cp.async.cg.shared.global [%0], [%1], 16;\n"                   \
                     "cp.async.cg.shared.global [%2], [%3], 16;"                     \
                     :: "r"(dw), "l"(sw), "r"(dw + 16), "l"(sw + 8));                \
    } while (0)

    LOAD_STAGE(0, 0);
    asm volatile("cp.async.commit_group;");

    int buf = 0;
    for (int kt = 0; kt < KT; kt++) {
        if (kt + 1 < KT) LOAD_STAGE(buf ^ 1, kt + 1);
        asm volatile("cp.async.commit_group;");
        asm volatile("cp.async.wait_group 1;");
        __syncthreads();

        #pragma unroll
        for (int ks = 0; ks < 2; ks++) {
            unsigned aF[4][4], bF[4][2];
            #pragma unroll
            for (int mt = 0; mt < 4; mt++) {
                unsigned addr = (unsigned)__cvta_generic_to_shared(
                    &As[buf][wm + mt * 16 + (lane & 15)][ks * 16 + (lane >> 4) * 8]);
                asm volatile("ldmatrix.sync.aligned.m8n8.x4.shared.b16 {%0,%1,%2,%3}, [%4];"
                    : "=r"(aF[mt][0]), "=r"(aF[mt][1]), "=r"(aF[mt][2]), "=r"(aF[mt][3])
                    : "r"(addr));
            }
            #pragma unroll
            for (int nt = 0; nt < 4; nt++) {
                unsigned addr = (unsigned)__cvta_generic_to_shared(
                    &Ws[buf][ks * 16 + (lane & 15)][wn + nt * 8]);
                asm volatile("ldmatrix.sync.aligned.m8n8.x2.trans.shared.b16 {%0,%1}, [%2];"
                    : "=r"(bF[nt][0]), "=r"(bF[nt][1]) : "r"(addr));
            }
            #pragma unroll
            for (int mt = 0; mt < 4; mt++)
                #pragma unroll
                for (int nt = 0; nt < 4; nt++) {
                    asm volatile(
                        "mma.sync.aligned.m16n8k16.row.col.f32.f16.f16.f32 "
                        "{%0,%1,%2,%3}, {%4,%5,%6,%7}, {%8,%9}, {%0,%1,%2,%3};"
                        : "+f"(acc[mt][nt][0]), "+f"(acc[mt][nt][1]),
                          "+f"(acc[mt][nt][2]), "+f"(acc[mt][nt][3])
                        : "r"(aF[mt][0]), "r"(aF[mt][1]), "r"(aF[mt][2]), "r"(aF[mt][3]),
                          "r"(bF[nt][0]), "r"(bF[nt][1]));
                }
        }
        buf ^= 1;
        __syncthreads();
    }

    #pragma unroll
    for (int mt = 0; mt < 4; mt++) {
        int r0 = m0 + wm + mt * 16 + (lane >> 2);
        #pragma unroll
        for (int nt = 0; nt < 4; nt++) {
            int c0 = n0 + wn + nt * 8 + (lane & 3) * 2;
            #pragma unroll
            for (int q = 0; q < 4; q++) {
                int r = r0 + (q >> 1) * 8;
                int c = c0 + (q & 1);
                if (c < Nc) {
                    float v = acc[mt][nt][q] + bias[c];
                    size_t off = (size_t)r * Nc + c;
                    if (epi == 0)      Cf[off] = v;
                    else if (epi == 1) Ch[off] = __float2half_rn(fmaxf(v, 0.f));
                    else if (epi == 2) Cf[off] = v + res[off];
                    else               Ch[off] = __float2half_rn(v);
                }
            }
        }
    }
}

// ---------------- self attention: per (b,h), Lq=Lk=10 ----------------
__global__ __launch_bounds__(128) void selfattn_k(const __half* __restrict__ Q,
                                                  const __half* __restrict__ KV,
                                                  const int* __restrict__ lengths,
                                                  __half* __restrict__ O) {
    int b = blockIdx.x, h = blockIdx.y;
    __shared__ float q[LL][65], k[LL][65], v[LL][65], s[LL][11];
    int tid = threadIdx.x;
    int len = lengths[b];
    for (int idx = tid; idx < LL * 64; idx += 128) {
        int i = idx >> 6, d = idx & 63;
        size_t qoff = ((size_t)(b * LL + i)) * DD + h * 64 + d;
        size_t koff = ((size_t)(b * LL + i)) * 1024 + h * 64 + d;
        q[i][d] = __half2float(Q[qoff]);
        k[i][d] = __half2float(KV[koff]);
        v[i][d] = __half2float(KV[koff + 512]);
    }
    __syncthreads();
    for (int idx = tid; idx < LL * LL; idx += 128) {
        int i = idx / LL, j = idx % LL;
        float acc = 0.f;
        #pragma unroll
        for (int d = 0; d < 64; d++) acc += q[i][d] * k[j][d];
        acc *= 0.125f;
        if (j > i || j >= len) acc = -1e30f;
        s[i][j] = acc;
    }
    __syncthreads();
    if (tid < LL) {
        float mx = -1e30f;
        #pragma unroll
        for (int j = 0; j < LL; j++) mx = fmaxf(mx, s[tid][j]);
        float sum = 0.f;
        #pragma unroll
        for (int j = 0; j < LL; j++) { float e = expf(s[tid][j] - mx); s[tid][j] = e; sum += e; }
        float inv = 1.0f / sum;
        #pragma unroll
        for (int j = 0; j < LL; j++) s[tid][j] *= inv;
    }
    __syncthreads();
    for (int idx = tid; idx < LL * 64; idx += 128) {
        int i = idx >> 6, d = idx & 63;
        float acc = 0.f;
        #pragma unroll
        for (int j = 0; j < LL; j++) acc += s[i][j] * v[j][d];
        O[((size_t)(b * LL + i)) * DD + h * 64 + d] = __float2half_rn(acc);
    }
}

// ---------------- cross attention: per (b,h), Lq=10, Lk=70 ----------------
__global__ __launch_bounds__(256) void crossattn_k(const __half* __restrict__ Q,
                                                   const __half* __restrict__ CKV,
                                                   __half* __restrict__ O) {
    int b = blockIdx.x, h = blockIdx.y;
    __shared__ float q[LL][65], kk[BOARD][65], vv[BOARD][65], s[LL][71];
    int tid = threadIdx.x;
    for (int idx = tid; idx < LL * 64; idx += 256) {
        int i = idx >> 6, d = idx & 63;
        q[i][d] = __half2float(Q[((size_t)(b * LL + i)) * DD + h * 64 + d]);
    }
    for (int idx = tid; idx < BOARD * 64; idx += 256) {
        int j = idx >> 6, d = idx & 63;
        size_t off = ((size_t)(b * BOARD + j)) * 1024 + h * 64 + d;
        kk[j][d] = __half2float(CKV[off]);
        vv[j][d] = __half2float(CKV[off + 512]);
    }
    __syncthreads();
    for (int idx = tid; idx < LL * BOARD; idx += 256) {
        int i = idx / BOARD, j = idx % BOARD;
        float acc = 0.f;
        #pragma unroll
        for (int d = 0; d < 64; d++) acc += q[i][d] * kk[j][d];
        s[i][j] = acc * 0.125f;
    }
    __syncthreads();
    if (tid < LL) {
        float mx = -1e30f;
        for (int j = 0; j < BOARD; j++) mx = fmaxf(mx, s[tid][j]);
        float sum = 0.f;
        for (int j = 0; j < BOARD; j++) { float e = expf(s[tid][j] - mx); s[tid][j] = e; sum += e; }
        float inv = 1.0f / sum;
        for (int j = 0; j < BOARD; j++) s[tid][j] *= inv;
    }
    __syncthreads();
    for (int idx = tid; idx < LL * 64; idx += 256) {
        int i = idx >> 6, d = idx & 63;
        float acc = 0.f;
        #pragma unroll
        for (int j = 0; j < BOARD; j++) acc += s[i][j] * vv[j][d];
        O[((size_t)(b * LL + i)) * DD + h * 64 + d] = __float2half_rn(acc);
    }
}

// ---------------- host ----------------
static void hgemm(const __half* A, const __half* W, const float* bias, const float* res,
                  float* Cf, __half* Ch, int M, int N, int K, int Nc, int epi) {
    dim3 grid(N / 128, M / 128);
    hgemm_k<<<grid, 256>>>(A, W, bias, res, Cf, Ch, M, N, K, Nc, epi);
}

extern "C" void kernel_launch(void* const* d_in, const int* in_sizes, int n_in,
                              void* d_out, int out_size) {
    const int*   moves   = (const int*)d_in[0];
    const int*   lengths = (const int*)d_in[1];
    const float* boards  = (const float*)d_in[2];
    const float* emb     = (const float*)d_in[3];
    const float* pos     = (const float*)d_in[4];
    const float* sa_ln_g = (const float*)d_in[5];
    const float* sa_ln_b = (const float*)d_in[6];
    const float* sa_wq   = (const float*)d_in[7];
    const float* sa_bq   = (const float*)d_in[8];
    const float* sa_wkv  = (const float*)d_in[9];
    const float* sa_bkv  = (const float*)d_in[10];
    const float* sa_wo   = (const float*)d_in[11];
    const float* sa_bo   = (const float*)d_in[12];
    const float* ca_ln_g = (const float*)d_in[13];
    const float* ca_ln_b = (const float*)d_in[14];
    const float* ca_wq   = (const float*)d_in[15];
    const float* ca_bq   = (const float*)d_in[16];
    const float* ca_wkv  = (const float*)d_in[17];
    const float* ca_bkv  = (const float*)d_in[18];
    const float* ca_wo   = (const float*)d_in[19];
    const float* ca_bo   = (const float*)d_in[20];
    const float* ff_ln_g = (const float*)d_in[21];
    const float* ff_ln_b = (const float*)d_in[22];
    const float* ff_w1   = (const float*)d_in[23];
    const float* ff_b1   = (const float*)d_in[24];
    const float* ff_w2   = (const float*)d_in[25];
    const float* ff_b2   = (const float*)d_in[26];
    const float* fin_g   = (const float*)d_in[27];
    const float* fin_b   = (const float*)d_in[28];
    const float* fc_w    = (const float*)d_in[29];
    const float* fc_b    = (const float*)d_in[30];
    float* out = (float*)d_out;

    float *px, *pfcb;
    __half *pxn, *pq, *pkv, *pao, *ph, *pckv, *pbf, *pwf;
    cudaGetSymbolAddress((void**)&px,   g_x);
    cudaGetSymbolAddress((void**)&pfcb, g_fcb);
    cudaGetSymbolAddress((void**)&pxn,  g_xn);
    cudaGetSymbolAddress((void**)&pq,   g_q);
    cudaGetSymbolAddress((void**)&pkv,  g_kv);
    cudaGetSymbolAddress((void**)&pao,  g_ao);
    cudaGetSymbolAddress((void**)&ph,   g_h);
    cudaGetSymbolAddress((void**)&pckv, g_ckv);
    cudaGetSymbolAddress((void**)&pbf,  g_bf);
    cudaGetSymbolAddress((void**)&pwf,  g_wf);

    // launches 1-5, so launch #6 (first hgemm) is the ncu target
    wconv_k<<<OFF_FCW / 512, 512>>>(sa_wq, sa_wkv, sa_wo, ca_wq, ca_wkv, ca_wo, ff_w1, ff_w2);
    bconv_k<<<(NBRD * DD) / 512, 512>>>(boards);
    pad_fc_k<<<(DD * VPAD) / 512, 512>>>(fc_w, fc_b);
    embed_k<<<NTOK, 128>>>(moves, emb, pos);

    for (int i = 0; i < NLAY; i++) {
        size_t oQ  = (size_t)i * 262144;
        size_t oKV = (size_t)i * 524288;
        size_t oF  = (size_t)i * 1048576;

        // ---- self attention ----
        ln_k<<<NTOK, 256>>>(px, sa_ln_g + i * DD, sa_ln_b + i * DD, pxn);
        hgemm(pxn, pwf + OFF_SAWQ + oQ,  sa_bq + i * 512,   nullptr, nullptr, pq,
              NTOK, 512, 512, 512, 3);
        hgemm(pxn, pwf + OFF_SAWKV + oKV, sa_bkv + i * 1024, nullptr, nullptr, pkv,
              NTOK, 1024, 512, 1024, 3);
        selfattn_k<<<dim3(BB, HH), 128>>>(pq, pkv, lengths, pao);
        hgemm(pao, pwf + OFF_SAWO + oQ,  sa_bo + i * DD,    px, px, nullptr,
              NTOK, 512, 512, 512, 2);

        // ---- cross attention ----
        ln_k<<<NTOK, 256>>>(px, ca_ln_g + i * DD, ca_ln_b + i * DD, pxn);
        hgemm(pxn, pwf + OFF_CAWQ + oQ,  ca_bq + i * 512,   nullptr, nullptr, pq,
              NTOK, 512, 512, 512, 3);
        hgemm(pbf, pwf + OFF_CAWKV + oKV, ca_bkv + i * 1024, nullptr, nullptr, pckv,
              NBRD, 1024, 512, 1024, 3);
        crossattn_k<<<dim3(BB, HH), 256>>>(pq, pckv, pao);
        hgemm(pao, pwf + OFF_CAWO + oQ,  ca_bo + i * DD,    px, px, nullptr,
              NTOK, 512, 512, 512, 2);

        // ---- FFN ----
        ln_k<<<NTOK, 256>>>(px, ff_ln_g + i * DD, ff_ln_b + i * DD, pxn);
        hgemm(pxn, pwf + OFF_FFW1 + oF,  ff_b1 + i * DI,    nullptr, nullptr, ph,
              NTOK, DI, 512, DI, 1);
        hgemm(ph, pwf + OFF_FFW2 + oF,   ff_b2 + i * DD,    px, px, nullptr,
              NTOK, 512, DI, 512, 2);
    }

    ln_k<<<NTOK, 256>>>(px, fin_g, fin_b, pxn);
    hgemm(pxn, pwf + OFF_FCW, pfcb, nullptr, out, nullptr, NTOK, VPAD, 512, VOCAB, 0);
}

// round 6
// speedup vs baseline: 5.0881x; 1.6213x over previous
#include <cuda_runtime.h>
#include <cuda_fp16.h>
#include <stdint.h>
#include <math.h>

#define BB 2048
#define LL 10
#define VOCAB 1974
#define DD 512
#define HH 8
#define DI 2048
#define NLAY 6
#define BOARD 70
#define NTOK (BB*LL)       /* 20480 */
#define NBRD (BB*BOARD)    /* 143360 */
#define VPAD 2048

#if defined(__CUDA_ARCH_FEAT_SM103_ALL) || defined(__CUDA_ARCH_FEAT_SM100_ALL) || defined(__CUDA_ARCH_FEAT_SM101_ALL)
#define TC5 1
#else
#define TC5 0
#endif

// ---- weight arena offsets (elements); same offsets for both layouts ----
#define OFF_SAWQ  0
#define OFF_SAWKV 1572864
#define OFF_SAWO  4718592
#define OFF_CAWQ  6291456
#define OFF_CAWKV 7864320
#define OFF_CAWO  11010048
#define OFF_FFW1  12582912
#define OFF_FFW2  18874368
#define OFF_FCW   25165824
#define WTOT      26214400

// ---------------- scratch (static device buffers) ----------------
__device__ float  g_x  [NTOK*DD];
__device__ float  g_fcb[VPAD];
__device__ __half g_xn [NTOK*DD];
__device__ __half g_q  [NTOK*DD];
__device__ __half g_kv [NTOK*1024];
__device__ __half g_ao [NTOK*DD];
__device__ __half g_h  [NTOK*DI];
__device__ __half g_ckv[(size_t)NBRD*1024];
__device__ __half g_bf [(size_t)NBRD*DD];
__device__ __half g_wf [WTOT];     // [K,N] layout (mma.sync fallback)
__device__ __half g_wt [WTOT];     // [N,K] layout (tcgen05)

// ---------------- prep: weights -> both fp16 layouts (one launch) ----------------
__global__ void wprep_k(const float* __restrict__ sawq, const float* __restrict__ sawkv,
                        const float* __restrict__ sawo, const float* __restrict__ cawq,
                        const float* __restrict__ cawkv, const float* __restrict__ cawo,
                        const float* __restrict__ ffw1, const float* __restrict__ ffw2,
                        const float* __restrict__ fcw) {
    size_t i = (size_t)blockIdx.x * blockDim.x + threadIdx.x;
    if (i >= WTOT) return;
    const float* src; size_t off, rb; int Kd, Nd, fc = 0;
    if      (i < OFF_SAWKV) { src = sawq;  off = i - OFF_SAWQ;  rb = OFF_SAWQ;  Kd = 512;  Nd = 512;  }
    else if (i < OFF_SAWO)  { src = sawkv; off = i - OFF_SAWKV; rb = OFF_SAWKV; Kd = 512;  Nd = 1024; }
    else if (i < OFF_CAWQ)  { src = sawo;  off = i - OFF_SAWO;  rb = OFF_SAWO;  Kd = 512;  Nd = 512;  }
    else if (i < OFF_CAWKV) { src = cawq;  off = i - OFF_CAWQ;  rb = OFF_CAWQ;  Kd = 512;  Nd = 512;  }
    else if (i < OFF_CAWO)  { src = cawkv; off = i - OFF_CAWKV; rb = OFF_CAWKV; Kd = 512;  Nd = 1024; }
    else if (i < OFF_FFW1)  { src = cawo;  off = i - OFF_CAWO;  rb = OFF_CAWO;  Kd = 512;  Nd = 512;  }
    else if (i < OFF_FFW2)  { src = ffw1;  off = i - OFF_FFW1;  rb = OFF_FFW1;  Kd = 512;  Nd = 2048; }
    else if (i < OFF_FCW)   { src = ffw2;  off = i - OFF_FFW2;  rb = OFF_FFW2;  Kd = 2048; Nd = 512;  }
    else                    { src = fcw;   off = i - OFF_FCW;   rb = OFF_FCW;   Kd = 512;  Nd = VPAD; fc = 1; }
    size_t per = (size_t)Kd * Nd;
    size_t l = off / per, rem = off - l * per;
    int n = (int)(rem / Kd), k = (int)(rem % Kd);
    float v;
    if (fc) v = (n < VOCAB) ? src[(size_t)k * VOCAB + n] : 0.f;
    else    v = src[l * per + (size_t)k * Nd + n];
    __half h = __float2half_rn(v);
    g_wt[i] = h;                                  // [N,K] coalesced
    g_wf[rb + l * per + (size_t)k * Nd + n] = h;  // [K,N]
}

__global__ void bconv_k(const float* __restrict__ boards) {
    size_t i = (size_t)blockIdx.x * blockDim.x + threadIdx.x;
    g_bf[i] = __float2half_rn(boards[i]);
}

// fcb copy + embedding, one launch
__global__ void misc_k(const float* __restrict__ fcb, const int* __restrict__ moves,
                       const float* __restrict__ emb, const float* __restrict__ pos) {
    size_t i = (size_t)blockIdx.x * blockDim.x + threadIdx.x;
    if (i < VPAD) g_fcb[i] = (i < VOCAB) ? fcb[i] : 0.f;
    if (i < (size_t)NTOK * DD) {
        int tok = (int)(i / DD), d = (int)(i % DD);
        g_x[i] = emb[(size_t)moves[tok] * DD + d] * 22.62741699796952f
               + pos[(size_t)(tok % LL) * DD + d];
    }
}

// ---------------- layernorm -> fp16 ----------------
__global__ __launch_bounds__(256) void ln_k(const float* __restrict__ X,
                                            const float* __restrict__ g,
                                            const float* __restrict__ b,
                                            __half* __restrict__ Y) {
    int row = blockIdx.x;
    const float2* x2 = (const float2*)(X + (size_t)row * DD);
    float2 v = x2[threadIdx.x];
    float s  = v.x + v.y;
    float ss = v.x * v.x + v.y * v.y;
    #pragma unroll
    for (int o = 16; o; o >>= 1) {
        s  += __shfl_down_sync(0xffffffffu, s,  o);
        ss += __shfl_down_sync(0xffffffffu, ss, o);
    }
    __shared__ float rs[8], rss[8];
    int w = threadIdx.x >> 5;
    if ((threadIdx.x & 31) == 0) { rs[w] = s; rss[w] = ss; }
    __syncthreads();
    if (threadIdx.x == 0) {
        float a = 0.f, c = 0.f;
        #pragma unroll
        for (int i = 0; i < 8; i++) { a += rs[i]; c += rss[i]; }
        rs[0] = a; rss[0] = c;
    }
    __syncthreads();
    float mean = rs[0] * (1.0f / DD);
    float var  = rss[0] * (1.0f / DD) - mean * mean;
    float rstd = rsqrtf(var + 1e-5f);
    float2 gg = ((const float2*)g)[threadIdx.x];
    float2 bb = ((const float2*)b)[threadIdx.x];
    size_t base = (size_t)row * DD + threadIdx.x * 2;
    Y[base]     = __float2half_rn((v.x - mean) * rstd * gg.x + bb.x);
    Y[base + 1] = __float2half_rn((v.y - mean) * rstd * gg.y + bb.y);
}

// ================= tcgen05 helpers (compiled only under TC5) =================
#if TC5
__device__ __forceinline__ uint32_t elect1() {
    uint32_t p;
    asm volatile("{\n\t.reg .pred p;\n\telect.sync _|p, 0xFFFFFFFF;\n\tselp.b32 %0, 1, 0, p;\n\t}"
                 : "=r"(p));
    return p;
}
#endif

#define MB_WAIT(mbar, ph) do {                                                        \
    uint32_t _d;                                                                      \
    do {                                                                              \
        asm volatile("{\n\t.reg .pred p;\n\t"                                         \
            "mbarrier.try_wait.parity.acquire.cta.shared::cta.b64 p, [%1], %2, 0x989680;\n\t" \
            "selp.b32 %0, 1, 0, p;\n\t}"                                              \
            : "=r"(_d) : "r"(mbar), "r"((uint32_t)(ph)) : "memory");                  \
    } while (!_d);                                                                    \
} while (0)

// SW128 K-major descriptor base: layout=SW128(2), version=1, SBO=64, LBO=1
#define DESC_BASE ((2ull<<61)|(1ull<<46)|(64ull<<32)|(1ull<<16))
// idesc kind::f16: dtype=F32, atype=btype=F16(0), N=128 (bits17), M=128 (bits24)
#define IDESC_F16 ((1u<<4) | (16u<<17) | (8u<<24))

#define TG_SMEM 66560

// ---------------- unified GEMM: C[M,Nc] = A[M,K] @ W ----------------
// W = [K,N] layout (fallback); Wt = [N,K] layout (tcgen05). Same math.
// epi: 0 +bias->f32  1 relu(+bias)->f16  2 +bias+res->f32  3 +bias->f16
__global__ __launch_bounds__(256, 2) void tgemm_k(
    const __half* __restrict__ A, const __half* __restrict__ W,
    const __half* __restrict__ Wt,
    const float* __restrict__ bias, const float* __restrict__ res,
    float* __restrict__ Cf, __half* __restrict__ Ch,
    int M, int N, int K, int Nc, int epi)
{
    extern __shared__ __align__(16) char smem[];
    const int tid  = threadIdx.x;
    const int lane = tid & 31;
    const int warp = tid >> 5;
    const int m0 = blockIdx.y * 128, n0 = blockIdx.x * 128;

#if TC5
    // ================= tcgen05 path =================
    const uint32_t sb = (uint32_t)__cvta_generic_to_shared(smem);
    const uint32_t MB   = sb + 16;
    const uint32_t SM_A = sb + 1024;
    const uint32_t SM_B = sb + 1024 + 32768;

    if (warp == 0) {
        asm volatile("tcgen05.alloc.cta_group::1.sync.aligned.shared::cta.b32 [%0], 128;"
                     :: "r"(sb) : "memory");
        asm volatile("tcgen05.relinquish_alloc_permit.cta_group::1.sync.aligned;");
    }
    if (tid == 0)
        asm volatile("mbarrier.init.shared.b64 [%0], 1;" :: "r"(MB) : "memory");
    __syncthreads();
    uint32_t tmem;
    asm volatile("ld.shared.b32 %0, [%1];" : "=r"(tmem) : "r"(sb));

    const __half* Ab = A  + (size_t)m0 * K;
    const __half* Bb = Wt + (size_t)n0 * K;
    const int KT = K >> 6;

    // tile loader: 128 rows x 64 halves (128B rows), SW128 swizzle, for A and B
    #define LOAD_T(kt, dA, dB) do {                                                   \
        const __half* aS = Ab + (kt) * 64;                                            \
        const __half* bS = Bb + (kt) * 64;                                            \
        for (int ch = tid; ch < 1024; ch += 256) {                                    \
            int row = ch >> 3;                                                        \
            int cb  = (ch & 7) << 4;                                                  \
            int bo  = (row << 7) + cb;                                                \
            int sw  = bo ^ ((bo >> 3) & 0x70);                                        \
            asm volatile("cp.async.cg.shared.global [%0], [%1], 16;"                  \
                :: "r"((dA) + sw), "l"((const void*)(aS + (size_t)row * K + (cb >> 1))) : "memory"); \
            asm volatile("cp.async.cg.shared.global [%0], [%1], 16;"                  \
                :: "r"((dB) + sw), "l"((const void*)(bS + (size_t)row * K + (cb >> 1))) : "memory"); \
        }                                                                             \
        asm volatile("cp.async.commit_group;" ::: "memory");                          \
    } while (0)

    LOAD_T(0, SM_A, SM_B);

    for (int kt = 0; kt < KT; kt++) {
        if (kt >= 1) MB_WAIT(MB, (kt - 1) & 1);     // mma kt-1 done -> its buffers free
        if (kt + 1 < KT) {
            LOAD_T(kt + 1, SM_A + ((kt + 1) & 1) * 16384, SM_B + ((kt + 1) & 1) * 16384);
            asm volatile("cp.async.wait_group 1;" ::: "memory");
        } else {
            asm volatile("cp.async.wait_group 0;" ::: "memory");
        }
        asm volatile("fence.proxy.async.shared::cta;" ::: "memory");
        __syncthreads();
        if (warp == 0 && elect1()) {
            uint64_t ad = DESC_BASE | (uint64_t)(((SM_A + (kt & 1) * 16384) >> 4) & 0x3FFF);
            uint64_t bd = DESC_BASE | (uint64_t)(((SM_B + (kt & 1) * 16384) >> 4) & 0x3FFF);
            #pragma unroll
            for (int s = 0; s < 4; s++) {
                uint32_t en = (kt > 0 || s > 0) ? 1u : 0u;
                asm volatile(
                    "{\n\t.reg .pred p;\n\tsetp.ne.u32 p, %5, 0;\n\t"
                    "tcgen05.mma.cta_group::1.kind::f16 [%0], %1, %2, %3, {%4,%4,%4,%4}, p;\n\t}"
                    :: "r"(tmem), "l"(ad + s * 2), "l"(bd + s * 2),
                       "r"(IDESC_F16), "r"(0u), "r"(en) : "memory");
            }
            asm volatile(
                "tcgen05.commit.cta_group::1.mbarrier::arrive::one.shared::cluster.b64 [%0];"
                :: "r"(MB) : "memory");
        }
    }

    MB_WAIT(MB, (KT - 1) & 1);
    asm volatile("tcgen05.fence::after_thread_sync;" ::: "memory");
    __syncthreads();

    // epilogue: 128x32 chunks through smem for coalesced writes
    float* osm = (float*)(smem + 1024);
    for (int cb = 0; cb < 128; cb += 32) {
        if (tid < 128) {
            uint32_t dr[32];
            asm volatile(
                "tcgen05.ld.sync.aligned.32x32b.x32.b32 "
                "{%0,%1,%2,%3,%4,%5,%6,%7,%8,%9,%10,%11,%12,%13,%14,%15,"
                "%16,%17,%18,%19,%20,%21,%22,%23,%24,%25,%26,%27,%28,%29,%30,%31}, [%32];"
                : "=r"(dr[0]),"=r"(dr[1]),"=r"(dr[2]),"=r"(dr[3]),"=r"(dr[4]),"=r"(dr[5]),
                  "=r"(dr[6]),"=r"(dr[7]),"=r"(dr[8]),"=r"(dr[9]),"=r"(dr[10]),"=r"(dr[11]),
                  "=r"(dr[12]),"=r"(dr[13]),"=r"(dr[14]),"=r"(dr[15]),"=r"(dr[16]),"=r"(dr[17]),
                  "=r"(dr[18]),"=r"(dr[19]),"=r"(dr[20]),"=r"(dr[21]),"=r"(dr[22]),"=r"(dr[23]),
                  "=r"(dr[24]),"=r"(dr[25]),"=r"(dr[26]),"=r"(dr[27]),"=r"(dr[28]),"=r"(dr[29]),
                  "=r"(dr[30]),"=r"(dr[31])
                : "r"(tmem + cb));
            asm volatile("tcgen05.wait::ld.sync.aligned;" ::: "memory");
            int r = warp * 32 + lane;
            #pragma unroll
            for (int c = 0; c < 32; c++) osm[r * 33 + c] = __uint_as_float(dr[c]);
        }
        __syncthreads();
        int col = n0 + cb + lane;
        for (int rr = warp; rr < 128; rr += 8) {
            if (col < Nc) {
                float v = osm[rr * 33 + lane] + bias[col];
                size_t off = (size_t)(m0 + rr) * Nc + col;
                if (epi == 0)      Cf[off] = v;
                else if (epi == 1) Ch[off] = __float2half_rn(fmaxf(v, 0.f));
                else if (epi == 2) Cf[off] = v + res[off];
                else               Ch[off] = __float2half_rn(v);
            }
        }
        __syncthreads();
    }

    if (tid == 0)
        asm volatile("mbarrier.inval.shared.b64 [%0];" :: "r"(MB) : "memory");
    __syncthreads();
    if (warp == 0)
        asm volatile("tcgen05.dealloc.cta_group::1.sync.aligned.b32 %0, 128;" :: "r"(tmem));
    #undef LOAD_T

#else
    // ================= mma.sync fallback (proven R4 body) =================
    __half* AsB = (__half*)smem;              // [2][128][40]
    __half* WsB = (__half*)(smem + 20480);    // [2][32][136]
    #define ASO(s,r,c) (((s)*128+(r))*40+(c))
    #define WSO(s,r,c) (((s)*32+(r))*136+(c))

    const int wm = (warp & 1) * 64;
    const int wn = (warp >> 1) * 32;
    const int arow = tid >> 1, acol = (tid & 1) * 16;
    const int wrow = tid >> 3, wcol = (tid & 7) * 16;

    const __half* Abase = A + (size_t)(m0 + arow) * K + acol;
    const __half* Wbase = W + (size_t)wrow * N + n0 + wcol;

    float acc[4][4][4];
    #pragma unroll
    for (int i = 0; i < 4; i++)
        #pragma unroll
        for (int j = 0; j < 4; j++)
            #pragma unroll
            for (int q = 0; q < 4; q++) acc[i][j][q] = 0.f;

    const int KT = K >> 5;

    #define LOAD_STAGE(s, kt) do {                                                   \
        unsigned da = (unsigned)__cvta_generic_to_shared(&AsB[ASO(s, arow, acol)]);  \
        const __half* sa = Abase + (kt) * 32;                                        \
        asm volatile("cp.async.cg.shared.global [%0], [%1], 16;\n"                   \
                     "cp.async.cg.shared.global [%2], [%3], 16;"                     \
                     :: "r"(da), "l"(sa), "r"(da + 16), "l"(sa + 8));                \
        unsigned dw = (unsigned)__cvta_generic_to_shared(&WsB[WSO(s, wrow, wcol)]);  \
        const __half* sw = Wbase + (size_t)((kt) * 32) * N;                          \
        asm volatile("cp.async.cg.shared.global [%0], [%1], 16;\n"                   \
                     "cp.async.cg.shared.global [%2], [%3], 16;"                     \
                     :: "r"(dw), "l"(sw), "r"(dw + 16), "l"(sw + 8));                \
    } while (0)

    LOAD_STAGE(0, 0);
    asm volatile("cp.async.commit_group;");

    int buf = 0;
    for (int kt = 0; kt < KT; kt++) {
        if (kt + 1 < KT) LOAD_STAGE(buf ^ 1, kt + 1);
        asm volatile("cp.async.commit_group;");
        asm volatile("cp.async.wait_group 1;");
        __syncthreads();

        #pragma unroll
        for (int ks = 0; ks < 2; ks++) {
            unsigned aF[4][4], bF[4][2];
            #pragma unroll
            for (int mt = 0; mt < 4; mt++) {
                unsigned addr = (unsigned)__cvta_generic_to_shared(
                    &AsB[ASO(buf, wm + mt * 16 + (lane & 15), ks * 16 + (lane >> 4) * 8)]);
                asm volatile("ldmatrix.sync.aligned.m8n8.x4.shared.b16 {%0,%1,%2,%3}, [%4];"
                    : "=r"(aF[mt][0]), "=r"(aF[mt][1]), "=r"(aF[mt][2]), "=r"(aF[mt][3])
                    : "r"(addr));
            }
            #pragma unroll
            for (int nt = 0; nt < 4; nt++) {
                unsigned addr = (unsigned)__cvta_generic_to_shared(
                    &WsB[WSO(buf, ks * 16 + (lane & 15), wn + nt * 8)]);
                asm volatile("ldmatrix.sync.aligned.m8n8.x2.trans.shared.b16 {%0,%1}, [%2];"
                    : "=r"(bF[nt][0]), "=r"(bF[nt][1]) : "r"(addr));
            }
            #pragma unroll
            for (int mt = 0; mt < 4; mt++)
                #pragma unroll
                for (int nt = 0; nt < 4; nt++) {
                    asm volatile(
                        "mma.sync.aligned.m16n8k16.row.col.f32.f16.f16.f32 "
                        "{%0,%1,%2,%3}, {%4,%5,%6,%7}, {%8,%9}, {%0,%1,%2,%3};"
                        : "+f"(acc[mt][nt][0]), "+f"(acc[mt][nt][1]),
                          "+f"(acc[mt][nt][2]), "+f"(acc[mt][nt][3])
                        : "r"(aF[mt][0]), "r"(aF[mt][1]), "r"(aF[mt][2]), "r"(aF[mt][3]),
                          "r"(bF[nt][0]), "r"(bF[nt][1]));
                }
        }
        buf ^= 1;
        __syncthreads();
    }

    #pragma unroll
    for (int mt = 0; mt < 4; mt++) {
        int r0 = m0 + wm + mt * 16 + (lane >> 2);
        #pragma unroll
        for (int nt = 0; nt < 4; nt++) {
            int c0 = n0 + wn + nt * 8 + (lane & 3) * 2;
            #pragma unroll
            for (int q = 0; q < 4; q++) {
                int r = r0 + (q >> 1) * 8;
                int c = c0 + (q & 1);
                if (c < Nc) {
                    float v = acc[mt][nt][q] + bias[c];
                    size_t off = (size_t)r * Nc + c;
                    if (epi == 0)      Cf[off] = v;
                    else if (epi == 1) Ch[off] = __float2half_rn(fmaxf(v, 0.f));
                    else if (epi == 2) Cf[off] = v + res[off];
                    else               Ch[off] = __float2half_rn(v);
                }
            }
        }
    }
    #undef LOAD_STAGE
    #undef ASO
    #undef WSO
#endif
}

// ---------------- self attention: per (b,h), Lq=Lk=10 ----------------
__global__ __launch_bounds__(128) void selfattn_k(const __half* __restrict__ Q,
                                                  const __half* __restrict__ KV,
                                                  const int* __restrict__ lengths,
                                                  __half* __restrict__ O) {
    int b = blockIdx.x, h = blockIdx.y;
    __shared__ float q[LL][65], k[LL][65], v[LL][65], s[LL][11];
    int tid = threadIdx.x;
    int len = lengths[b];
    for (int idx = tid; idx < LL * 64; idx += 128) {
        int i = idx >> 6, d = idx & 63;
        size_t qoff = ((size_t)(b * LL + i)) * DD + h * 64 + d;
        size_t koff = ((size_t)(b * LL + i)) * 1024 + h * 64 + d;
        q[i][d] = __half2float(Q[qoff]);
        k[i][d] = __half2float(KV[koff]);
        v[i][d] = __half2float(KV[koff + 512]);
    }
    __syncthreads();
    for (int idx = tid; idx < LL * LL; idx += 128) {
        int i = idx / LL, j = idx % LL;
        float acc = 0.f;
        #pragma unroll
        for (int d = 0; d < 64; d++) acc += q[i][d] * k[j][d];
        acc *= 0.125f;
        if (j > i || j >= len) acc = -1e30f;
        s[i][j] = acc;
    }
    __syncthreads();
    if (tid < LL) {
        float mx = -1e30f;
        #pragma unroll
        for (int j = 0; j < LL; j++) mx = fmaxf(mx, s[tid][j]);
        float sum = 0.f;
        #pragma unroll
        for (int j = 0; j < LL; j++) { float e = expf(s[tid][j] - mx); s[tid][j] = e; sum += e; }
        float inv = 1.0f / sum;
        #pragma unroll
        for (int j = 0; j < LL; j++) s[tid][j] *= inv;
    }
    __syncthreads();
    for (int idx = tid; idx < LL * 64; idx += 128) {
        int i = idx >> 6, d = idx & 63;
        float acc = 0.f;
        #pragma unroll
        for (int j = 0; j < LL; j++) acc += s[i][j] * v[j][d];
        O[((size_t)(b * LL + i)) * DD + h * 64 + d] = __float2half_rn(acc);
    }
}

// ---------------- cross attention: per (b,h), Lq=10, Lk=70 ----------------
__global__ __launch_bounds__(256) void crossattn_k(const __half* __restrict__ Q,
                                                   const __half* __restrict__ CKV,
                                                   __half* __restrict__ O) {
    int b = blockIdx.x, h = blockIdx.y;
    __shared__ float q[LL][65], kk[BOARD][65], vv[BOARD][65], s[LL][71];
    int tid = threadIdx.x;
    for (int idx = tid; idx < LL * 64; idx += 256) {
        int i = idx >> 6, d = idx & 63;
        q[i][d] = __half2float(Q[((size_t)(b * LL + i)) * DD + h * 64 + d]);
    }
    for (int idx = tid; idx < BOARD * 64; idx += 256) {
        int j = idx >> 6, d = idx & 63;
        size_t off = ((size_t)(b * BOARD + j)) * 1024 + h * 64 + d;
        kk[j][d] = __half2float(CKV[off]);
        vv[j][d] = __half2float(CKV[off + 512]);
    }
    __syncthreads();
    for (int idx = tid; idx < LL * BOARD; idx += 256) {
        int i = idx / BOARD, j = idx % BOARD;
        float acc = 0.f;
        #pragma unroll
        for (int d = 0; d < 64; d++) acc += q[i][d] * kk[j][d];
        s[i][j] = acc * 0.125f;
    }
    __syncthreads();
    if (tid < LL) {
        float mx = -1e30f;
        for (int j = 0; j < BOARD; j++) mx = fmaxf(mx, s[tid][j]);
        float sum = 0.f;
        for (int j = 0; j < BOARD; j++) { float e = expf(s[tid][j] - mx); s[tid][j] = e; sum += e; }
        float inv = 1.0f / sum;
        for (int j = 0; j < BOARD; j++) s[tid][j] *= inv;
    }
    __syncthreads();
    for (int idx = tid; idx < LL * 64; idx += 256) {
        int i = idx >> 6, d = idx & 63;
        float acc = 0.f;
        #pragma unroll
        for (int j = 0; j < BOARD; j++) acc += s[i][j] * vv[j][d];
        O[((size_t)(b * LL + i)) * DD + h * 64 + d] = __float2half_rn(acc);
    }
}

// ---------------- host ----------------
static __half *s_wf, *s_wt;

static void tgemm(const __half* A, size_t woff, const float* bias, const float* res,
                  float* Cf, __half* Ch, int M, int N, int K, int Nc, int epi) {
    dim3 grid(N / 128, M / 128);
    tgemm_k<<<grid, 256, TG_SMEM>>>(A, s_wf + woff, s_wt + woff, bias, res, Cf, Ch,
                                    M, N, K, Nc, epi);
}

extern "C" void kernel_launch(void* const* d_in, const int* in_sizes, int n_in,
                              void* d_out, int out_size) {
    const int*   moves   = (const int*)d_in[0];
    const int*   lengths = (const int*)d_in[1];
    const float* boards  = (const float*)d_in[2];
    const float* emb     = (const float*)d_in[3];
    const float* pos     = (const float*)d_in[4];
    const float* sa_ln_g = (const float*)d_in[5];
    const float* sa_ln_b = (const float*)d_in[6];
    const float* sa_wq   = (const float*)d_in[7];
    const float* sa_bq   = (const float*)d_in[8];
    const float* sa_wkv  = (const float*)d_in[9];
    const float* sa_bkv  = (const float*)d_in[10];
    const float* sa_wo   = (const float*)d_in[11];
    const float* sa_bo   = (const float*)d_in[12];
    const float* ca_ln_g = (const float*)d_in[13];
    const float* ca_ln_b = (const float*)d_in[14];
    const float* ca_wq   = (const float*)d_in[15];
    const float* ca_bq   = (const float*)d_in[16];
    const float* ca_wkv  = (const float*)d_in[17];
    const float* ca_bkv  = (const float*)d_in[18];
    const float* ca_wo   = (const float*)d_in[19];
    const float* ca_bo   = (const float*)d_in[20];
    const float* ff_ln_g = (const float*)d_in[21];
    const float* ff_ln_b = (const float*)d_in[22];
    const float* ff_w1   = (const float*)d_in[23];
    const float* ff_b1   = (const float*)d_in[24];
    const float* ff_w2   = (const float*)d_in[25];
    const float* ff_b2   = (const float*)d_in[26];
    const float* fin_g   = (const float*)d_in[27];
    const float* fin_b   = (const float*)d_in[28];
    const float* fc_w    = (const float*)d_in[29];
    const float* fc_b    = (const float*)d_in[30];
    float* out = (float*)d_out;

    cudaFuncSetAttribute(tgemm_k, cudaFuncAttributeMaxDynamicSharedMemorySize, TG_SMEM);

    float *px, *pfcb;
    __half *pxn, *pq, *pkv, *pao, *ph, *pckv, *pbf;
    cudaGetSymbolAddress((void**)&px,   g_x);
    cudaGetSymbolAddress((void**)&pfcb, g_fcb);
    cudaGetSymbolAddress((void**)&pxn,  g_xn);
    cudaGetSymbolAddress((void**)&pq,   g_q);
    cudaGetSymbolAddress((void**)&pkv,  g_kv);
    cudaGetSymbolAddress((void**)&pao,  g_ao);
    cudaGetSymbolAddress((void**)&ph,   g_h);
    cudaGetSymbolAddress((void**)&pckv, g_ckv);
    cudaGetSymbolAddress((void**)&pbf,  g_bf);
    cudaGetSymbolAddress((void**)&s_wf, g_wf);
    cudaGetSymbolAddress((void**)&s_wt, g_wt);

    // prep: exactly 3 launches, then the flagship caKV GEMM at launch #4 (ncu target)
    wprep_k<<<WTOT / 512, 512>>>(sa_wq, sa_wkv, sa_wo, ca_wq, ca_wkv, ca_wo,
                                 ff_w1, ff_w2, fc_w);
    bconv_k<<<((size_t)NBRD * DD) / 512, 512>>>(boards);
    misc_k<<<(NTOK * DD) / 512, 512>>>(fc_b, moves, emb, pos);

    // layer-0 cross-KV (depends only on boards) hoisted here
    tgemm(pbf, OFF_CAWKV, ca_bkv, nullptr, nullptr, pckv, NBRD, 1024, 512, 1024, 3);

    for (int i = 0; i < NLAY; i++) {
        size_t oQ  = (size_t)i * 262144;
        size_t oKV = (size_t)i * 524288;
        size_t oF  = (size_t)i * 1048576;

        // ---- self attention ----
        ln_k<<<NTOK, 256>>>(px, sa_ln_g + i * DD, sa_ln_b + i * DD, pxn);
        tgemm(pxn, OFF_SAWQ + oQ,  sa_bq + i * 512,   nullptr, nullptr, pq,
              NTOK, 512, 512, 512, 3);
        tgemm(pxn, OFF_SAWKV + oKV, sa_bkv + i * 1024, nullptr, nullptr, pkv,
              NTOK, 1024, 512, 1024, 3);
        selfattn_k<<<dim3(BB, HH), 128>>>(pq, pkv, lengths, pao);
        tgemm(pao, OFF_SAWO + oQ,  sa_bo + i * DD,    px, px, nullptr,
              NTOK, 512, 512, 512, 2);

        // ---- cross attention ----
        ln_k<<<NTOK, 256>>>(px, ca_ln_g + i * DD, ca_ln_b + i * DD, pxn);
        tgemm(pxn, OFF_CAWQ + oQ,  ca_bq + i * 512,   nullptr, nullptr, pq,
              NTOK, 512, 512, 512, 3);
        if (i > 0)
            tgemm(pbf, OFF_CAWKV + oKV, ca_bkv + i * 1024, nullptr, nullptr, pckv,
                  NBRD, 1024, 512, 1024, 3);
        crossattn_k<<<dim3(BB, HH), 256>>>(pq, pckv, pao);
        tgemm(pao, OFF_CAWO + oQ,  ca_bo + i * DD,    px, px, nullptr,
              NTOK, 512, 512, 512, 2);

        // ---- FFN ----
        ln_k<<<NTOK, 256>>>(px, ff_ln_g + i * DD, ff_ln_b + i * DD, pxn);
        tgemm(pxn, OFF_FFW1 + oF,  ff_b1 + i * DI,    nullptr, nullptr, ph,
              NTOK, DI, 512, DI, 1);
        tgemm(ph, OFF_FFW2 + oF,   ff_b2 + i * DD,    px, px, nullptr,
              NTOK, 512, DI, 512, 2);
    }

    ln_k<<<NTOK, 256>>>(px, fin_g, fin_b, pxn);
    tgemm(pxn, OFF_FCW, pfcb, nullptr, out, nullptr, NTOK, VPAD, 512, VOCAB, 0);
}